// round 1
// baseline (speedup 1.0000x reference)
#include <cuda_runtime.h>
#include <math.h>

#define NN   50000
#define EE   800000
#define FIN  32
#define HH   64
#define H2   128
#define EDIM 16
#define GG   64
#define COUT 40
#define NPB  25
#define PCHUNK 256

// ---------------- scratch (no allocation allowed) ----------------
__device__ float g_h[NN * HH];      // node features (residual stream)
__device__ float g_z[NN * HH];      // post norm-act features
__device__ float g_num[NN * HH];    // softmax-agg numerator
__device__ float g_den[NN * HH];    // softmax-agg denominator
__device__ float g_hmid[NN * H2];   // MLP hidden
__device__ float g_sA[2][HH];
__device__ float g_qA[2][HH];
__device__ float g_sB[2][H2];
__device__ float g_qB[2][H2];
__device__ float g_pool[GG * HH];
__device__ float g_cnt[GG];

// ---------------- input linear: h = x @ W_in + b, plus global zero-init ----
__global__ void k_lin_in(const float* __restrict__ x,
                         const float* __restrict__ W,
                         const float* __restrict__ b) {
    __shared__ float Wsh[FIN * HH];
    __shared__ float xs[4][FIN];
    int tid = threadIdx.x;

    for (int i = tid; i < FIN * HH; i += 256) Wsh[i] = W[i];

    if (blockIdx.x == 0) {  // zero all small accumulators once per call
        for (int i = tid; i < 2 * HH; i += 256) { ((float*)g_sA)[i] = 0.f; ((float*)g_qA)[i] = 0.f; }
        for (int i = tid; i < 2 * H2; i += 256) { ((float*)g_sB)[i] = 0.f; ((float*)g_qB)[i] = 0.f; }
        for (int i = tid; i < GG * HH; i += 256) g_pool[i] = 0.f;
        if (tid < GG) g_cnt[tid] = 0.f;
    }

    int n0 = blockIdx.x * 4;
    if (tid < 128) {
        int nl = tid >> 5, k = tid & 31;
        int n = n0 + nl;
        xs[nl][k] = (n < NN) ? x[n * FIN + k] : 0.f;
    }
    __syncthreads();

    int i = tid >> 6, j = tid & 63;
    int n = n0 + i;
    if (n < NN) {
        float acc = b[j];
#pragma unroll
        for (int k = 0; k < FIN; k++) acc += xs[i][k] * Wsh[k * HH + j];
        g_h[n * HH + j] = acc;
    }
}

// ---------------- BN stats over g_h (64 features) ----------------
__global__ void k_statsA(int l) {
    int tid = threadIdx.x;
    int j = tid & (HH - 1);
    int rl = tid >> 6;  // 0..3
    float s = 0.f, q = 0.f;
    for (int r = blockIdx.x * 4 + rl; r < NN; r += gridDim.x * 4) {
        float v = g_h[r * HH + j];
        s += v; q += v * v;
    }
    __shared__ float sh[512];
    sh[tid] = s; sh[256 + tid] = q;
    __syncthreads();
    if (tid < HH) {
        float S = 0.f, Q = 0.f;
#pragma unroll
        for (int i = 0; i < 4; i++) { S += sh[i * HH + tid]; Q += sh[256 + i * HH + tid]; }
        atomicAdd(&g_sA[l][tid], S);
        atomicAdd(&g_qA[l][tid], Q);
    }
}

// ---------------- BN stats over g_hmid (128 features) ----------------
__global__ void k_statsB(int l) {
    int tid = threadIdx.x;
    int j = tid & (H2 - 1);
    int rl = tid >> 7;  // 0..1
    float s = 0.f, q = 0.f;
    for (int r = blockIdx.x * 2 + rl; r < NN; r += gridDim.x * 2) {
        float v = g_hmid[r * H2 + j];
        s += v; q += v * v;
    }
    __shared__ float sh[512];
    sh[tid] = s; sh[256 + tid] = q;
    __syncthreads();
    if (tid < H2) {
        float S = sh[tid] + sh[H2 + tid];
        float Q = sh[256 + tid] + sh[256 + H2 + tid];
        atomicAdd(&g_sB[l][tid], S);
        atomicAdd(&g_qB[l][tid], Q);
    }
}

// ------- z = relu(BN(h)); also zero num/den accumulators ----------
__global__ void k_bnrelu(const float* __restrict__ gamma,
                         const float* __restrict__ beta, int l) {
    __shared__ float sc[HH], sf[HH];
    int tid = threadIdx.x;
    if (tid < HH) {
        float mu = g_sA[l][tid] * (1.f / NN);
        float var = g_qA[l][tid] * (1.f / NN) - mu * mu;
        float rs = rsqrtf(var + 1e-5f);
        float s = gamma[tid] * rs;
        sc[tid] = s;
        sf[tid] = beta[tid] - mu * s;
    }
    __syncthreads();
    int total = NN * HH;
    for (int i = blockIdx.x * blockDim.x + tid; i < total; i += gridDim.x * blockDim.x) {
        int j = i & (HH - 1);
        float v = g_h[i] * sc[j] + sf[j];
        g_z[i] = fmaxf(v, 0.f);
        g_num[i] = 0.f;
        g_den[i] = 0.f;
    }
}

// ------- fused edge kernel: edge-MLP + message + exp + atomic agg -------
__global__ void k_edge(const float* __restrict__ ea, const int* __restrict__ ei,
                       const float* __restrict__ W, const float* __restrict__ b,
                       const float* __restrict__ tptr) {
    __shared__ float Wsh[EDIM * HH];
    __shared__ float eas[4][EDIM];
    int tid = threadIdx.x;
    for (int i = tid; i < EDIM * HH; i += 256) Wsh[i] = W[i];
    float tc = tptr[0];
    int el = tid >> 6, j = tid & 63;
    float bj = b[j];
    int e_base = blockIdx.x * 32;
    for (int it = 0; it < 8; it++) {
        int eg = e_base + it * 4;
        __syncthreads();
        if (tid < 64) {
            int e = eg + (tid >> 4);
            eas[tid >> 4][tid & 15] = (e < EE) ? ea[e * EDIM + (tid & 15)] : 0.f;
        }
        __syncthreads();
        int e = eg + el;
        if (e < EE) {
            float acc = bj;
#pragma unroll
            for (int k = 0; k < EDIM; k++) acc += eas[el][k] * Wsh[k * HH + j];
            int src = ei[e], dst = ei[EE + e];
            float m = fmaxf(g_z[src * HH + j] + acc, 0.f) + 1e-7f;
            float ex = expf(m * tc);  // max-shift dropped: m in [1e-7, ~6], no overflow
            atomicAdd(&g_den[dst * HH + j], ex);
            atomicAdd(&g_num[dst * HH + j], ex * m);
        }
    }
}

// ------- agg finalize + root add + MLP layer 1 (64 -> 128) -------
__global__ void k_mlp1(const float* __restrict__ w1, const float* __restrict__ b1) {
    __shared__ float Wsh[HH * H2];  // 32KB
    __shared__ float outs[HH];
    int tid = threadIdx.x;  // 128
    for (int i = tid; i < HH * H2; i += 128) Wsh[i] = w1[i];
    float bj = b1[tid];
    int n0 = blockIdx.x * NPB;
    for (int it = 0; it < NPB; it++) {
        int n = n0 + it;
        if (n >= NN) break;
        __syncthreads();
        if (tid < HH) {
            int idx = n * HH + tid;
            outs[tid] = g_num[idx] / (g_den[idx] + 1e-16f) + g_z[idx];
        }
        __syncthreads();
        float acc = bj;
#pragma unroll
        for (int k = 0; k < HH; k++) acc += outs[k] * Wsh[k * H2 + tid];
        g_hmid[n * H2 + tid] = acc;
    }
}

// ------- BN2 + relu + MLP layer 2 (128 -> 64) + residual into g_h -------
__global__ void k_mlp2(const float* __restrict__ w2, const float* __restrict__ b2,
                       const float* __restrict__ gamma, const float* __restrict__ beta,
                       int l) {
    __shared__ float Wsh[H2 * HH];  // 32KB
    __shared__ float act[H2];
    __shared__ float red[H2];
    __shared__ float sc[H2], sf[H2];
    int tid = threadIdx.x;  // 128
    {
        float mu = g_sB[l][tid] * (1.f / NN);
        float var = g_qB[l][tid] * (1.f / NN) - mu * mu;
        float rs = rsqrtf(var + 1e-5f);
        float s = gamma[tid] * rs;
        sc[tid] = s;
        sf[tid] = beta[tid] - mu * s;
    }
    for (int i = tid; i < H2 * HH; i += 128) Wsh[i] = w2[i];
    int j = tid & 63, half = tid >> 6;
    int n0 = blockIdx.x * NPB;
    for (int it = 0; it < NPB; it++) {
        int n = n0 + it;
        if (n >= NN) break;
        __syncthreads();
        act[tid] = fmaxf(g_hmid[n * H2 + tid] * sc[tid] + sf[tid], 0.f);
        __syncthreads();
        float acc = 0.f;
#pragma unroll
        for (int k = 0; k < 64; k++) acc += act[half * 64 + k] * Wsh[(half * 64 + k) * HH + j];
        red[tid] = acc;
        __syncthreads();
        if (tid < HH) g_h[n * HH + tid] += b2[tid] + red[tid] + red[64 + tid];
    }
}

// ------- global mean pool (batch is sorted): block-chunked segment sum -------
__global__ void k_pool(const int* __restrict__ batch) {
    int j = threadIdx.x;  // 64
    int n0 = blockIdx.x * PCHUNK;
    if (n0 >= NN) return;
    int n1 = min(n0 + PCHUNK, NN);
    int cur = batch[n0];
    float s = 0.f, cnt = 0.f;
    for (int n = n0; n < n1; n++) {
        int b = batch[n];
        if (b != cur) {
            atomicAdd(&g_pool[cur * HH + j], s);
            if (j == 0) atomicAdd(&g_cnt[cur], cnt);
            s = 0.f; cnt = 0.f; cur = b;
        }
        s += g_h[n * HH + j];
        cnt += 1.f;
    }
    atomicAdd(&g_pool[cur * HH + j], s);
    if (j == 0) atomicAdd(&g_cnt[cur], cnt);
}

// ------- output: out = relu(pooled) @ W_out + b_out -------
__global__ void k_final(const float* __restrict__ W, const float* __restrict__ b,
                        float* __restrict__ out) {
    __shared__ float p[HH];
    int g = blockIdx.x, tid = threadIdx.x;  // 64
    float c = fmaxf(g_cnt[g], 1.f);
    p[tid] = fmaxf(g_pool[g * HH + tid] / c, 0.f);
    __syncthreads();
    if (tid < COUT) {
        float acc = b[tid];
#pragma unroll
        for (int k = 0; k < HH; k++) acc += p[k] * W[k * COUT + tid];
        out[g * COUT + tid] = acc;
    }
}

extern "C" void kernel_launch(void* const* d_in, const int* in_sizes, int n_in,
                              void* d_out, int out_size) {
    const float* x        = (const float*)d_in[0];
    const int*   ei       = (const int*)d_in[1];
    const float* ea       = (const float*)d_in[2];
    const int*   batch    = (const int*)d_in[3];
    const float* lin_in_w = (const float*)d_in[4];
    const float* lin_in_b = (const float*)d_in[5];
    const float* ng       = (const float*)d_in[6];
    const float* nb       = (const float*)d_in[7];
    const float* ew       = (const float*)d_in[8];
    const float* eb       = (const float*)d_in[9];
    const float* tt       = (const float*)d_in[10];
    const float* w1       = (const float*)d_in[11];
    const float* b1       = (const float*)d_in[12];
    const float* mg       = (const float*)d_in[13];
    const float* mb       = (const float*)d_in[14];
    const float* w2       = (const float*)d_in[15];
    const float* b2       = (const float*)d_in[16];
    const float* ow       = (const float*)d_in[17];
    const float* ob       = (const float*)d_in[18];
    float* out = (float*)d_out;

    k_lin_in<<<(NN + 3) / 4, 256>>>(x, lin_in_w, lin_in_b);
    for (int l = 0; l < 2; l++) {
        k_statsA<<<256, 256>>>(l);
        k_bnrelu<<<1024, 256>>>(ng + l * HH, nb + l * HH, l);
        k_edge<<<(EE + 31) / 32, 256>>>(ea, ei, ew + l * EDIM * HH, eb + l * HH, tt + l);
        k_mlp1<<<(NN + NPB - 1) / NPB, 128>>>(w1 + l * HH * H2, b1 + l * H2);
        k_statsB<<<256, 256>>>(l);
        k_mlp2<<<(NN + NPB - 1) / NPB, 128>>>(w2 + l * H2 * HH, b2 + l * HH,
                                              mg + l * H2, mb + l * H2, l);
    }
    k_pool<<<(NN + PCHUNK - 1) / PCHUNK, 64>>>(batch);
    k_final<<<GG, 64>>>(ow, ob, out);
}

// round 2
// speedup vs baseline: 1.3693x; 1.3693x over previous
#include <cuda_runtime.h>
#include <math.h>

#define NN   50000
#define EE   800000
#define FIN  32
#define HH   64
#define H2   128
#define EDIM 16
#define GG   64
#define COUT 40
#define PCHUNK 256
#define SCAN_T 1024

// ---------------- scratch (no allocation allowed) ----------------
__device__ float g_h[NN * HH];      // node features (residual stream)
__device__ float g_z[NN * HH];      // post norm-act features
__device__ float g_agg[NN * HH];    // softmax-agg output + root (MLP1 input)
__device__ float g_hmid[NN * H2];   // MLP hidden
__device__ float g_sA[2][HH];
__device__ float g_qA[2][HH];
__device__ float g_sB[2][H2];
__device__ float g_qB[2][H2];
__device__ float g_pool[GG * HH];
__device__ float g_cnt[GG];
// CSR scratch
__device__ int g_deg[NN];
__device__ int g_cur[NN];
__device__ int g_off[NN + 1];
__device__ int g_psrc[EE];
__device__ int g_peid[EE];

// ---------------- input linear: h = x @ W_in + b, plus global zero-init ----
__global__ void k_lin_in(const float* __restrict__ x,
                         const float* __restrict__ W,
                         const float* __restrict__ b) {
    __shared__ float Wsh[FIN * HH];
    __shared__ float xs[4][FIN];
    int tid = threadIdx.x;

    for (int i = tid; i < FIN * HH; i += 256) Wsh[i] = W[i];

    if (blockIdx.x == 0) {  // zero all small accumulators once per call
        for (int i = tid; i < 2 * HH; i += 256) { ((float*)g_sA)[i] = 0.f; ((float*)g_qA)[i] = 0.f; }
        for (int i = tid; i < 2 * H2; i += 256) { ((float*)g_sB)[i] = 0.f; ((float*)g_qB)[i] = 0.f; }
        for (int i = tid; i < GG * HH; i += 256) g_pool[i] = 0.f;
        if (tid < GG) g_cnt[tid] = 0.f;
    }

    int n0 = blockIdx.x * 4;
    if (tid < 128) {
        int nl = tid >> 5, k = tid & 31;
        int n = n0 + nl;
        xs[nl][k] = (n < NN) ? x[n * FIN + k] : 0.f;
    }
    __syncthreads();

    int i = tid >> 6, j = tid & 63;
    int n = n0 + i;
    if (n < NN) {
        float acc = b[j];
#pragma unroll
        for (int k = 0; k < FIN; k++) acc += xs[i][k] * Wsh[k * HH + j];
        g_h[n * HH + j] = acc;
    }
}

// ---------------- CSR build ----------------
__global__ void k_csr_zero() {
    for (int i = blockIdx.x * blockDim.x + threadIdx.x; i < NN; i += gridDim.x * blockDim.x) {
        g_deg[i] = 0; g_cur[i] = 0;
    }
}

__global__ void k_hist(const int* __restrict__ ei) {
    for (int e = blockIdx.x * blockDim.x + threadIdx.x; e < EE; e += gridDim.x * blockDim.x)
        atomicAdd(&g_deg[ei[EE + e]], 1);
}

__global__ void k_scan() {
    __shared__ int part[SCAN_T];
    int t = threadIdx.x;
    const int CH = (NN + SCAN_T - 1) / SCAN_T;  // 49
    int beg = t * CH, end = min(beg + CH, NN);
    int s = 0;
    for (int i = beg; i < end; i++) s += g_deg[i];
    part[t] = s;
    __syncthreads();
    // inclusive Hillis-Steele scan
    for (int off = 1; off < SCAN_T; off <<= 1) {
        int v = (t >= off) ? part[t - off] : 0;
        __syncthreads();
        part[t] += v;
        __syncthreads();
    }
    int run = (t == 0) ? 0 : part[t - 1];
    for (int i = beg; i < end; i++) { g_off[i] = run; run += g_deg[i]; }
    if (t == SCAN_T - 1) g_off[NN] = part[SCAN_T - 1];
}

__global__ void k_scatter(const int* __restrict__ ei) {
    for (int e = blockIdx.x * blockDim.x + threadIdx.x; e < EE; e += gridDim.x * blockDim.x) {
        int d = ei[EE + e];
        int p = atomicAdd(&g_cur[d], 1);
        int idx = g_off[d] + p;
        g_psrc[idx] = ei[e];
        g_peid[idx] = e;
    }
}

// ---------------- BN stats over g_h (64 features) ----------------
__global__ void k_statsA(int l) {
    int tid = threadIdx.x;
    int j = tid & (HH - 1);
    int rl = tid >> 6;  // 0..3
    float s = 0.f, q = 0.f;
    for (int r = blockIdx.x * 4 + rl; r < NN; r += gridDim.x * 4) {
        float v = g_h[r * HH + j];
        s += v; q += v * v;
    }
    __shared__ float sh[512];
    sh[tid] = s; sh[256 + tid] = q;
    __syncthreads();
    if (tid < HH) {
        float S = 0.f, Q = 0.f;
#pragma unroll
        for (int i = 0; i < 4; i++) { S += sh[i * HH + tid]; Q += sh[256 + i * HH + tid]; }
        atomicAdd(&g_sA[l][tid], S);
        atomicAdd(&g_qA[l][tid], Q);
    }
}

// ---------------- BN stats over g_hmid (128 features) ----------------
__global__ void k_statsB(int l) {
    int tid = threadIdx.x;
    int j = tid & (H2 - 1);
    int rl = tid >> 7;  // 0..1
    float s = 0.f, q = 0.f;
    for (int r = blockIdx.x * 2 + rl; r < NN; r += gridDim.x * 2) {
        float v = g_hmid[r * H2 + j];
        s += v; q += v * v;
    }
    __shared__ float sh[512];
    sh[tid] = s; sh[256 + tid] = q;
    __syncthreads();
    if (tid < H2) {
        float S = sh[tid] + sh[H2 + tid];
        float Q = sh[256 + tid] + sh[256 + H2 + tid];
        atomicAdd(&g_sB[l][tid], S);
        atomicAdd(&g_qB[l][tid], Q);
    }
}

// ------- z = relu(BN(h)) ----------
__global__ void k_bnrelu(const float* __restrict__ gamma,
                         const float* __restrict__ beta, int l) {
    __shared__ float sc[HH], sf[HH];
    int tid = threadIdx.x;
    if (tid < HH) {
        float mu = g_sA[l][tid] * (1.f / NN);
        float var = g_qA[l][tid] * (1.f / NN) - mu * mu;
        float rs = rsqrtf(var + 1e-5f);
        float s = gamma[tid] * rs;
        sc[tid] = s;
        sf[tid] = beta[tid] - mu * s;
    }
    __syncthreads();
    int total = NN * HH;
    for (int i = blockIdx.x * blockDim.x + tid; i < total; i += gridDim.x * blockDim.x) {
        int j = i & (HH - 1);
        float v = g_h[i] * sc[j] + sf[j];
        g_z[i] = fmaxf(v, 0.f);
    }
}

// ------- CSR-gather: edge-MLP + message + softmax-agg + root add -------
// one warp per node, 2 features per lane, edge-MLP column weights in registers
__global__ void k_gather(const float* __restrict__ ea,
                         const float* __restrict__ W,
                         const float* __restrict__ b,
                         const float* __restrict__ tptr) {
    int warp = (blockIdx.x * blockDim.x + threadIdx.x) >> 5;
    int lane = threadIdx.x & 31;
    if (warp >= NN) return;
    int n = warp;
    float tc = tptr[0];
    int j0 = lane, j1 = lane + 32;
    float W0[EDIM], W1[EDIM];
#pragma unroll
    for (int k = 0; k < EDIM; k++) { W0[k] = W[k * HH + j0]; W1[k] = W[k * HH + j1]; }
    float b0 = b[j0], b1 = b[j1];
    int beg = g_off[n], end = g_off[n + 1];
    float den0 = 0.f, num0 = 0.f, den1 = 0.f, num1 = 0.f;
    for (int i = beg; i < end; i++) {
        int src = g_psrc[i];
        int eid = g_peid[i];
        const float4* eav4 = (const float4*)(ea + (size_t)eid * EDIM);
        float eav[EDIM];
        *(float4*)&eav[0]  = eav4[0];
        *(float4*)&eav[4]  = eav4[1];
        *(float4*)&eav[8]  = eav4[2];
        *(float4*)&eav[12] = eav4[3];
        float emb0 = b0, emb1 = b1;
#pragma unroll
        for (int k = 0; k < EDIM; k++) { emb0 += eav[k] * W0[k]; emb1 += eav[k] * W1[k]; }
        float z0 = g_z[src * HH + j0];
        float z1 = g_z[src * HH + j1];
        float m0 = fmaxf(z0 + emb0, 0.f) + 1e-7f;
        float m1 = fmaxf(z1 + emb1, 0.f) + 1e-7f;
        float ex0 = __expf(m0 * tc);   // no max-shift: m in [1e-7, ~6], no overflow
        float ex1 = __expf(m1 * tc);
        den0 += ex0; num0 += ex0 * m0;
        den1 += ex1; num1 += ex1 * m1;
    }
    g_agg[n * HH + j0] = num0 / (den0 + 1e-16f) + g_z[n * HH + j0];
    g_agg[n * HH + j1] = num1 / (den1 + 1e-16f) + g_z[n * HH + j1];
}

// ------- MLP1 as register-tiled GEMM: g_hmid[N,128] = g_agg[N,64] @ w1 + b1 ----
// 64-node tile, 256 threads, 8x4 outputs/thread, A in shared, W via L1 LDG.128
__global__ void k_mlp1(const float* __restrict__ w1, const float* __restrict__ b1) {
    __shared__ float As[64 * 65];
    int tid = threadIdx.x;  // 256
    int n0 = blockIdx.x * 64;
    for (int idx = tid; idx < 64 * 64; idx += 256) {
        int r = idx >> 6, k = idx & 63;
        int n = n0 + r;
        As[r * 65 + k] = (n < NN) ? g_agg[n * HH + k] : 0.f;
    }
    __syncthreads();
    int tx = tid & 31, ty = tid >> 5;       // tx: 0..31, ty: 0..7
    int col = tx * 4, row0 = ty * 8;
    float acc[8][4];
#pragma unroll
    for (int i = 0; i < 8; i++) { acc[i][0] = acc[i][1] = acc[i][2] = acc[i][3] = 0.f; }
#pragma unroll 4
    for (int k = 0; k < 64; k++) {
        float4 bv = *(const float4*)&w1[k * H2 + col];
        float a[8];
#pragma unroll
        for (int i = 0; i < 8; i++) a[i] = As[(row0 + i) * 65 + k];
#pragma unroll
        for (int i = 0; i < 8; i++) {
            acc[i][0] += a[i] * bv.x; acc[i][1] += a[i] * bv.y;
            acc[i][2] += a[i] * bv.z; acc[i][3] += a[i] * bv.w;
        }
    }
    float4 bb = *(const float4*)&b1[col];
#pragma unroll
    for (int i = 0; i < 8; i++) {
        int n = n0 + row0 + i;
        if (n < NN) {
            float4 o;
            o.x = acc[i][0] + bb.x; o.y = acc[i][1] + bb.y;
            o.z = acc[i][2] + bb.z; o.w = acc[i][3] + bb.w;
            *(float4*)&g_hmid[n * H2 + col] = o;
        }
    }
}

// ------- MLP2 GEMM with fused BN2+ReLU on A-load and residual epilogue ------
// g_h[N,64] += relu(BN(g_hmid)) @ w2 + b2 ; 64-node tile, 128 threads, 8x4/thread
__global__ void k_mlp2(const float* __restrict__ w2, const float* __restrict__ b2,
                       const float* __restrict__ gamma, const float* __restrict__ beta,
                       int l) {
    __shared__ float As[64 * H2];   // 32KB
    __shared__ float sc[H2], sf[H2];
    int tid = threadIdx.x;  // 128
    {
        float mu = g_sB[l][tid] * (1.f / NN);
        float var = g_qB[l][tid] * (1.f / NN) - mu * mu;
        float rs = rsqrtf(var + 1e-5f);
        float s = gamma[tid] * rs;
        sc[tid] = s;
        sf[tid] = beta[tid] - mu * s;
    }
    __syncthreads();
    int n0 = blockIdx.x * 64;
    for (int idx = tid; idx < 64 * H2; idx += 128) {
        int r = idx >> 7, k = idx & 127;
        int n = n0 + r;
        float v = (n < NN) ? g_hmid[n * H2 + k] : 0.f;
        As[r * H2 + k] = fmaxf(v * sc[k] + sf[k], 0.f);
    }
    __syncthreads();
    int tx = tid & 15, ty = tid >> 4;   // tx: 0..15, ty: 0..7
    int col = tx * 4, row0 = ty * 8;
    float acc[8][4];
#pragma unroll
    for (int i = 0; i < 8; i++) { acc[i][0] = acc[i][1] = acc[i][2] = acc[i][3] = 0.f; }
#pragma unroll 4
    for (int k = 0; k < H2; k++) {
        float4 bv = *(const float4*)&w2[k * HH + col];
        float a[8];
#pragma unroll
        for (int i = 0; i < 8; i++) a[i] = As[(row0 + i) * H2 + k];
#pragma unroll
        for (int i = 0; i < 8; i++) {
            acc[i][0] += a[i] * bv.x; acc[i][1] += a[i] * bv.y;
            acc[i][2] += a[i] * bv.z; acc[i][3] += a[i] * bv.w;
        }
    }
    float4 bb = *(const float4*)&b2[col];
#pragma unroll
    for (int i = 0; i < 8; i++) {
        int n = n0 + row0 + i;
        if (n < NN) {
            float4 h = *(const float4*)&g_h[n * HH + col];
            h.x += acc[i][0] + bb.x; h.y += acc[i][1] + bb.y;
            h.z += acc[i][2] + bb.z; h.w += acc[i][3] + bb.w;
            *(float4*)&g_h[n * HH + col] = h;
        }
    }
}

// ------- global mean pool (batch is sorted): block-chunked segment sum -------
__global__ void k_pool(const int* __restrict__ batch) {
    int j = threadIdx.x;  // 64
    int n0 = blockIdx.x * PCHUNK;
    if (n0 >= NN) return;
    int n1 = min(n0 + PCHUNK, NN);
    int cur = batch[n0];
    float s = 0.f, cnt = 0.f;
    for (int n = n0; n < n1; n++) {
        int b = batch[n];
        if (b != cur) {
            atomicAdd(&g_pool[cur * HH + j], s);
            if (j == 0) atomicAdd(&g_cnt[cur], cnt);
            s = 0.f; cnt = 0.f; cur = b;
        }
        s += g_h[n * HH + j];
        cnt += 1.f;
    }
    atomicAdd(&g_pool[cur * HH + j], s);
    if (j == 0) atomicAdd(&g_cnt[cur], cnt);
}

// ------- output: out = relu(pooled) @ W_out + b_out -------
__global__ void k_final(const float* __restrict__ W, const float* __restrict__ b,
                        float* __restrict__ out) {
    __shared__ float p[HH];
    int g = blockIdx.x, tid = threadIdx.x;  // 64
    float c = fmaxf(g_cnt[g], 1.f);
    p[tid] = fmaxf(g_pool[g * HH + tid] / c, 0.f);
    __syncthreads();
    if (tid < COUT) {
        float acc = b[tid];
#pragma unroll
        for (int k = 0; k < HH; k++) acc += p[k] * W[k * COUT + tid];
        out[g * COUT + tid] = acc;
    }
}

extern "C" void kernel_launch(void* const* d_in, const int* in_sizes, int n_in,
                              void* d_out, int out_size) {
    const float* x        = (const float*)d_in[0];
    const int*   ei       = (const int*)d_in[1];
    const float* ea       = (const float*)d_in[2];
    const int*   batch    = (const int*)d_in[3];
    const float* lin_in_w = (const float*)d_in[4];
    const float* lin_in_b = (const float*)d_in[5];
    const float* ng       = (const float*)d_in[6];
    const float* nb       = (const float*)d_in[7];
    const float* ew       = (const float*)d_in[8];
    const float* eb       = (const float*)d_in[9];
    const float* tt       = (const float*)d_in[10];
    const float* w1       = (const float*)d_in[11];
    const float* b1       = (const float*)d_in[12];
    const float* mg       = (const float*)d_in[13];
    const float* mb       = (const float*)d_in[14];
    const float* w2       = (const float*)d_in[15];
    const float* b2       = (const float*)d_in[16];
    const float* ow       = (const float*)d_in[17];
    const float* ob       = (const float*)d_in[18];
    float* out = (float*)d_out;

    k_lin_in<<<(NN + 3) / 4, 256>>>(x, lin_in_w, lin_in_b);
    // CSR build (dst is layer-invariant)
    k_csr_zero<<<64, 256>>>();
    k_hist<<<512, 256>>>(ei);
    k_scan<<<1, SCAN_T>>>();
    k_scatter<<<512, 256>>>(ei);
    for (int l = 0; l < 2; l++) {
        k_statsA<<<256, 256>>>(l);
        k_bnrelu<<<1024, 256>>>(ng + l * HH, nb + l * HH, l);
        k_gather<<<(NN * 32 + 255) / 256, 256>>>(ea, ew + l * EDIM * HH, eb + l * HH, tt + l);
        k_mlp1<<<(NN + 63) / 64, 256>>>(w1 + l * HH * H2, b1 + l * H2);
        k_statsB<<<256, 256>>>(l);
        k_mlp2<<<(NN + 63) / 64, 128>>>(w2 + l * H2 * HH, b2 + l * HH,
                                        mg + l * H2, mb + l * H2, l);
    }
    k_pool<<<(NN + PCHUNK - 1) / PCHUNK, 64>>>(batch);
    k_final<<<GG, 64>>>(ow, ob, out);
}

// round 4
// speedup vs baseline: 1.6507x; 1.2055x over previous
#include <cuda_runtime.h>
#include <math.h>

#define NN   50000
#define EE   800000
#define FIN  32
#define HH   64
#define H2   128
#define EDIM 16
#define GG   64
#define COUT 40
#define PCHUNK 128

// ---------------- scratch (no allocation allowed) ----------------
__device__ float g_h[NN * HH];      // node features (residual stream)
__device__ float g_z[NN * HH];      // post norm-act features
__device__ float g_agg[NN * HH];    // softmax-agg output + root (MLP1 input)
__device__ float g_hmid[NN * H2];   // MLP hidden
__device__ float g_sA[3][HH];
__device__ float g_qA[3][HH];
__device__ float g_sB[2][H2];
__device__ float g_qB[2][H2];
__device__ float g_pool[GG * HH];
__device__ float g_cnt[GG];
// CSR scratch
__device__ int g_deg[NN];
__device__ int g_cur[NN];
__device__ int g_off[NN + 1];
__device__ int2 g_pe[EE];           // {src, eid}
__device__ int g_bsum[64];
__device__ int g_bbase[64];

// ---------------- zero all accumulators ----------------
__global__ void k_zero() {
    int i = blockIdx.x * blockDim.x + threadIdx.x;
    if (i < NN) { g_deg[i] = 0; g_cur[i] = 0; }
    if (i < 3 * HH) { ((float*)g_sA)[i] = 0.f; ((float*)g_qA)[i] = 0.f; }
    if (i < 2 * H2) { ((float*)g_sB)[i] = 0.f; ((float*)g_qB)[i] = 0.f; }
    if (i < GG * HH) g_pool[i] = 0.f;
    if (i < GG) g_cnt[i] = 0.f;
}

// -------- input linear: h = x @ W_in + b, fused statsA(0) epilogue --------
// 16 nodes per block, 256 threads: thread (ig, j) computes 4 nodes' feature j
__global__ void k_lin_in(const float* __restrict__ x,
                         const float* __restrict__ W,
                         const float* __restrict__ b) {
    __shared__ float Wsh[FIN * HH];       // 8KB
    __shared__ float xs[16][FIN + 1];
    __shared__ float red[4][HH];
    int tid = threadIdx.x;
    int j = tid & 63, ig = tid >> 6;      // ig: 0..3

    for (int i = tid; i < FIN * HH; i += 256) Wsh[i] = W[i];
    int n0 = blockIdx.x * 16;             // 3125 blocks * 16 = 50000 exactly
    for (int i = tid; i < 16 * FIN; i += 256) {
        int nl = i >> 5, k = i & 31;
        xs[nl][k] = x[(n0 + nl) * FIN + k];
    }
    __syncthreads();

    float bj = b[j];
    float acc[4];
#pragma unroll
    for (int r = 0; r < 4; r++) acc[r] = bj;
#pragma unroll
    for (int k = 0; k < FIN; k++) {
        float wv = Wsh[k * HH + j];
#pragma unroll
        for (int r = 0; r < 4; r++) acc[r] += xs[ig * 4 + r][k] * wv;
    }
    float s = 0.f, q = 0.f;
#pragma unroll
    for (int r = 0; r < 4; r++) {
        g_h[(n0 + ig * 4 + r) * HH + j] = acc[r];
        s += acc[r]; q += acc[r] * acc[r];
    }
    red[ig][j] = s;
    __syncthreads();
    if (ig == 0) {
        float S = red[0][j] + red[1][j] + red[2][j] + red[3][j];
        atomicAdd(&g_sA[0][j], S);
    }
    __syncthreads();
    red[ig][j] = q;
    __syncthreads();
    if (ig == 0) {
        float Q = red[0][j] + red[1][j] + red[2][j] + red[3][j];
        atomicAdd(&g_qA[0][j], Q);
    }
}

// ---------------- CSR build ----------------
__global__ void k_hist(const int* __restrict__ ei) {
    int t = blockIdx.x * blockDim.x + threadIdx.x;
    if (t * 4 >= EE) return;
    int4 d4 = ((const int4*)(ei + EE))[t];
    atomicAdd(&g_deg[d4.x], 1);
    atomicAdd(&g_deg[d4.y], 1);
    atomicAdd(&g_deg[d4.z], 1);
    atomicAdd(&g_deg[d4.w], 1);
}

__global__ void k_scanA() {
    __shared__ int sh[1024];
    int t = threadIdx.x;
    int i = blockIdx.x * 1024 + t;
    int v = (i < NN) ? g_deg[i] : 0;
    sh[t] = v;
    __syncthreads();
    for (int off = 1; off < 1024; off <<= 1) {
        int u = (t >= off) ? sh[t - off] : 0;
        __syncthreads();
        sh[t] += u;
        __syncthreads();
    }
    if (i < NN) g_off[i] = sh[t] - v;   // exclusive (local)
    if (t == 1023) g_bsum[blockIdx.x] = sh[t];
}

__global__ void k_scanB(int nblk) {
    __shared__ int sh[64];
    int t = threadIdx.x;
    int v = (t < nblk) ? g_bsum[t] : 0;
    sh[t] = v;
    __syncthreads();
    for (int off = 1; off < 64; off <<= 1) {
        int u = (t >= off) ? sh[t - off] : 0;
        __syncthreads();
        sh[t] += u;
        __syncthreads();
    }
    if (t < nblk) g_bbase[t] = sh[t] - v;
}

__global__ void k_scanC() {
    int i = blockIdx.x * 1024 + threadIdx.x;
    if (i < NN) g_off[i] += g_bbase[blockIdx.x];
    if (i == 0) g_off[NN] = EE;
}

__global__ void k_scatter(const int* __restrict__ ei) {
    int t = blockIdx.x * blockDim.x + threadIdx.x;
    if (t * 4 >= EE) return;
    int4 s4 = ((const int4*)ei)[t];
    int4 d4 = ((const int4*)(ei + EE))[t];
    int e0 = t * 4;
    int p, d;
    d = d4.x; p = atomicAdd(&g_cur[d], 1); g_pe[g_off[d] + p] = make_int2(s4.x, e0);
    d = d4.y; p = atomicAdd(&g_cur[d], 1); g_pe[g_off[d] + p] = make_int2(s4.y, e0 + 1);
    d = d4.z; p = atomicAdd(&g_cur[d], 1); g_pe[g_off[d] + p] = make_int2(s4.z, e0 + 2);
    d = d4.w; p = atomicAdd(&g_cur[d], 1); g_pe[g_off[d] + p] = make_int2(s4.w, e0 + 3);
}

// ------- z = relu(BN(h)), float4 vectorized ----------
__global__ void k_bnrelu(const float* __restrict__ gamma,
                         const float* __restrict__ beta, int l) {
    __shared__ float sc[HH], sf[HH];
    int tid = threadIdx.x;
    if (tid < HH) {
        float mu = g_sA[l][tid] * (1.f / NN);
        float var = g_qA[l][tid] * (1.f / NN) - mu * mu;
        float rs = rsqrtf(var + 1e-5f);
        float s = gamma[tid] * rs;
        sc[tid] = s;
        sf[tid] = beta[tid] - mu * s;
    }
    __syncthreads();
    int total = NN * HH / 4;
    for (int i = blockIdx.x * blockDim.x + tid; i < total; i += gridDim.x * blockDim.x) {
        int j = (i * 4) & 63;
        float4 v = ((const float4*)g_h)[i];
        float4 o;
        o.x = fmaxf(v.x * sc[j]     + sf[j],     0.f);
        o.y = fmaxf(v.y * sc[j + 1] + sf[j + 1], 0.f);
        o.z = fmaxf(v.z * sc[j + 2] + sf[j + 2], 0.f);
        o.w = fmaxf(v.w * sc[j + 3] + sf[j + 3], 0.f);
        ((float4*)g_z)[i] = o;
    }
}

// ------- CSR-gather: edge-MLP + message + softmax-agg + root add -------
__global__ void k_gather(const float* __restrict__ ea,
                         const float* __restrict__ W,
                         const float* __restrict__ b,
                         const float* __restrict__ tptr) {
    int warp = (blockIdx.x * blockDim.x + threadIdx.x) >> 5;
    int lane = threadIdx.x & 31;
    if (warp >= NN) return;
    int n = warp;
    float tc = tptr[0];
    int j0 = lane, j1 = lane + 32;
    float W0[EDIM], W1[EDIM];
#pragma unroll
    for (int k = 0; k < EDIM; k++) { W0[k] = W[k * HH + j0]; W1[k] = W[k * HH + j1]; }
    float b0 = b[j0], b1 = b[j1];
    int beg = g_off[n], end = g_off[n + 1];
    float den0 = 0.f, num0 = 0.f, den1 = 0.f, num1 = 0.f;
#pragma unroll 2
    for (int i = beg; i < end; i++) {
        int2 pe = g_pe[i];
        int src = pe.x, eid = pe.y;
        const float4* eav4 = (const float4*)(ea + (size_t)eid * EDIM);
        float eav[EDIM];
        *(float4*)&eav[0]  = eav4[0];
        *(float4*)&eav[4]  = eav4[1];
        *(float4*)&eav[8]  = eav4[2];
        *(float4*)&eav[12] = eav4[3];
        float z0 = g_z[src * HH + j0];
        float z1 = g_z[src * HH + j1];
        float emb0 = b0, emb1 = b1;
#pragma unroll
        for (int k = 0; k < EDIM; k++) { emb0 += eav[k] * W0[k]; emb1 += eav[k] * W1[k]; }
        float m0 = fmaxf(z0 + emb0, 0.f) + 1e-7f;
        float m1 = fmaxf(z1 + emb1, 0.f) + 1e-7f;
        float ex0 = __expf(m0 * tc);   // no max-shift: m in [1e-7, ~6], no overflow
        float ex1 = __expf(m1 * tc);
        den0 += ex0; num0 += ex0 * m0;
        den1 += ex1; num1 += ex1 * m1;
    }
    g_agg[n * HH + j0] = num0 / (den0 + 1e-16f) + g_z[n * HH + j0];
    g_agg[n * HH + j1] = num1 / (den1 + 1e-16f) + g_z[n * HH + j1];
}

// ------- MLP1 GEMM (64-node tile, 8x4/thread) with fused statsB epilogue ----
__global__ void k_mlp1(const float* __restrict__ w1, const float* __restrict__ b1, int l) {
    __shared__ float As[64 * 65];       // 16.6KB
    __shared__ float sred[8][H2];       // 4KB
    int tid = threadIdx.x;  // 256
    int n0 = blockIdx.x * 64;
    for (int idx = tid; idx < 64 * 64; idx += 256) {
        int r = idx >> 6, k = idx & 63;
        int n = n0 + r;
        As[r * 65 + k] = (n < NN) ? g_agg[n * HH + k] : 0.f;
    }
    __syncthreads();
    int tx = tid & 31, ty = tid >> 5;
    int col = tx * 4, row0 = ty * 8;
    float acc[8][4];
#pragma unroll
    for (int i = 0; i < 8; i++) { acc[i][0] = acc[i][1] = acc[i][2] = acc[i][3] = 0.f; }
#pragma unroll 4
    for (int k = 0; k < 64; k++) {
        float4 bv = *(const float4*)&w1[k * H2 + col];
        float a[8];
#pragma unroll
        for (int i = 0; i < 8; i++) a[i] = As[(row0 + i) * 65 + k];
#pragma unroll
        for (int i = 0; i < 8; i++) {
            acc[i][0] += a[i] * bv.x; acc[i][1] += a[i] * bv.y;
            acc[i][2] += a[i] * bv.z; acc[i][3] += a[i] * bv.w;
        }
    }
    float4 bb = *(const float4*)&b1[col];
    float s[4] = {0.f, 0.f, 0.f, 0.f}, q[4] = {0.f, 0.f, 0.f, 0.f};
#pragma unroll
    for (int i = 0; i < 8; i++) {
        int n = n0 + row0 + i;
        if (n < NN) {
            float4 o;
            o.x = acc[i][0] + bb.x; o.y = acc[i][1] + bb.y;
            o.z = acc[i][2] + bb.z; o.w = acc[i][3] + bb.w;
            *(float4*)&g_hmid[n * H2 + col] = o;
            s[0] += o.x; s[1] += o.y; s[2] += o.z; s[3] += o.w;
            q[0] += o.x * o.x; q[1] += o.y * o.y; q[2] += o.z * o.z; q[3] += o.w * o.w;
        }
    }
    // statsB reduction: over ty (8) for each column
#pragma unroll
    for (int c = 0; c < 4; c++) sred[ty][col + c] = s[c];
    __syncthreads();
    if (tid < H2) {
        float S = 0.f;
#pragma unroll
        for (int i = 0; i < 8; i++) S += sred[i][tid];
        atomicAdd(&g_sB[l][tid], S);
    }
    __syncthreads();
#pragma unroll
    for (int c = 0; c < 4; c++) sred[ty][col + c] = q[c];
    __syncthreads();
    if (tid < H2) {
        float Q = 0.f;
#pragma unroll
        for (int i = 0; i < 8; i++) Q += sred[i][tid];
        atomicAdd(&g_qB[l][tid], Q);
    }
}

// ------- MLP2 GEMM with fused BN2+ReLU, residual, and statsA(l+1) epilogue --
__global__ void k_mlp2(const float* __restrict__ w2, const float* __restrict__ b2,
                       const float* __restrict__ gamma, const float* __restrict__ beta,
                       int l) {
    __shared__ float As[64 * H2];       // 32KB
    __shared__ float sc[H2], sf[H2];
    __shared__ float sred[8][HH];       // 2KB
    int tid = threadIdx.x;  // 128
    {
        float mu = g_sB[l][tid] * (1.f / NN);
        float var = g_qB[l][tid] * (1.f / NN) - mu * mu;
        float rs = rsqrtf(var + 1e-5f);
        float s = gamma[tid] * rs;
        sc[tid] = s;
        sf[tid] = beta[tid] - mu * s;
    }
    __syncthreads();
    int n0 = blockIdx.x * 64;
    for (int idx = tid; idx < 64 * H2; idx += 128) {
        int r = idx >> 7, k = idx & 127;
        int n = n0 + r;
        float v = (n < NN) ? g_hmid[n * H2 + k] : 0.f;
        As[r * H2 + k] = fmaxf(v * sc[k] + sf[k], 0.f);
    }
    __syncthreads();
    int tx = tid & 15, ty = tid >> 4;
    int col = tx * 4, row0 = ty * 8;
    float acc[8][4];
#pragma unroll
    for (int i = 0; i < 8; i++) { acc[i][0] = acc[i][1] = acc[i][2] = acc[i][3] = 0.f; }
#pragma unroll 4
    for (int k = 0; k < H2; k++) {
        float4 bv = *(const float4*)&w2[k * HH + col];
        float a[8];
#pragma unroll
        for (int i = 0; i < 8; i++) a[i] = As[(row0 + i) * H2 + k];
#pragma unroll
        for (int i = 0; i < 8; i++) {
            acc[i][0] += a[i] * bv.x; acc[i][1] += a[i] * bv.y;
            acc[i][2] += a[i] * bv.z; acc[i][3] += a[i] * bv.w;
        }
    }
    float4 bb = *(const float4*)&b2[col];
    float s[4] = {0.f, 0.f, 0.f, 0.f}, q[4] = {0.f, 0.f, 0.f, 0.f};
#pragma unroll
    for (int i = 0; i < 8; i++) {
        int n = n0 + row0 + i;
        if (n < NN) {
            float4 h = *(const float4*)&g_h[n * HH + col];
            h.x += acc[i][0] + bb.x; h.y += acc[i][1] + bb.y;
            h.z += acc[i][2] + bb.z; h.w += acc[i][3] + bb.w;
            *(float4*)&g_h[n * HH + col] = h;
            s[0] += h.x; s[1] += h.y; s[2] += h.z; s[3] += h.w;
            q[0] += h.x * h.x; q[1] += h.y * h.y; q[2] += h.z * h.z; q[3] += h.w * h.w;
        }
    }
    // statsA(l+1) reduction
#pragma unroll
    for (int c = 0; c < 4; c++) sred[ty][col + c] = s[c];
    __syncthreads();
    if (tid < HH) {
        float S = 0.f;
#pragma unroll
        for (int i = 0; i < 8; i++) S += sred[i][tid];
        atomicAdd(&g_sA[l + 1][tid], S);
    }
    __syncthreads();
#pragma unroll
    for (int c = 0; c < 4; c++) sred[ty][col + c] = q[c];
    __syncthreads();
    if (tid < HH) {
        float Q = 0.f;
#pragma unroll
        for (int i = 0; i < 8; i++) Q += sred[i][tid];
        atomicAdd(&g_qA[l + 1][tid], Q);
    }
}

// ------- global mean pool (batch is sorted): block-chunked segment sum -------
__global__ void k_pool(const int* __restrict__ batch) {
    int j = threadIdx.x;  // 64
    int n0 = blockIdx.x * PCHUNK;
    if (n0 >= NN) return;
    int n1 = min(n0 + PCHUNK, NN);
    int cur = batch[n0];
    float s = 0.f, cnt = 0.f;
    for (int n = n0; n < n1; n++) {
        int b = batch[n];
        if (b != cur) {
            atomicAdd(&g_pool[cur * HH + j], s);
            if (j == 0) atomicAdd(&g_cnt[cur], cnt);
            s = 0.f; cnt = 0.f; cur = b;
        }
        s += g_h[n * HH + j];
        cnt += 1.f;
    }
    atomicAdd(&g_pool[cur * HH + j], s);
    if (j == 0) atomicAdd(&g_cnt[cur], cnt);
}

// ------- output: out = relu(pooled) @ W_out + b_out -------
__global__ void k_final(const float* __restrict__ W, const float* __restrict__ b,
                        float* __restrict__ out) {
    __shared__ float p[HH];
    int g = blockIdx.x, tid = threadIdx.x;  // 64
    float c = fmaxf(g_cnt[g], 1.f);
    p[tid] = fmaxf(g_pool[g * HH + tid] / c, 0.f);
    __syncthreads();
    if (tid < COUT) {
        float acc = b[tid];
#pragma unroll
        for (int k = 0; k < HH; k++) acc += p[k] * W[k * COUT + tid];
        out[g * COUT + tid] = acc;
    }
}

extern "C" void kernel_launch(void* const* d_in, const int* in_sizes, int n_in,
                              void* d_out, int out_size) {
    const float* x        = (const float*)d_in[0];
    const int*   ei       = (const int*)d_in[1];
    const float* ea       = (const float*)d_in[2];
    const int*   batch    = (const int*)d_in[3];
    const float* lin_in_w = (const float*)d_in[4];
    const float* lin_in_b = (const float*)d_in[5];
    const float* ng       = (const float*)d_in[6];
    const float* nb       = (const float*)d_in[7];
    const float* ew       = (const float*)d_in[8];
    const float* eb       = (const float*)d_in[9];
    const float* tt       = (const float*)d_in[10];
    const float* w1       = (const float*)d_in[11];
    const float* b1       = (const float*)d_in[12];
    const float* mg       = (const float*)d_in[13];
    const float* mb       = (const float*)d_in[14];
    const float* w2       = (const float*)d_in[15];
    const float* b2       = (const float*)d_in[16];
    const float* ow       = (const float*)d_in[17];
    const float* ob       = (const float*)d_in[18];
    float* out = (float*)d_out;

    const int SCAN_BLKS = (NN + 1023) / 1024;   // 49

    k_zero<<<(NN + 511) / 512, 512>>>();
    k_lin_in<<<NN / 16, 256>>>(x, lin_in_w, lin_in_b);
    k_hist<<<(EE / 4 + 255) / 256, 256>>>(ei);
    k_scanA<<<SCAN_BLKS, 1024>>>();
    k_scanB<<<1, 64>>>(SCAN_BLKS);
    k_scanC<<<SCAN_BLKS, 1024>>>();
    k_scatter<<<(EE / 4 + 255) / 256, 256>>>(ei);
    for (int l = 0; l < 2; l++) {
        k_bnrelu<<<1024, 256>>>(ng + l * HH, nb + l * HH, l);
        k_gather<<<(NN * 32 + 255) / 256, 256>>>(ea, ew + l * EDIM * HH, eb + l * HH, tt + l);
        k_mlp1<<<(NN + 63) / 64, 256>>>(w1 + l * HH * H2, b1 + l * H2, l);
        k_mlp2<<<(NN + 63) / 64, 128>>>(w2 + l * H2 * HH, b2 + l * HH,
                                        mg + l * H2, mb + l * H2, l);
    }
    k_pool<<<(NN + PCHUNK - 1) / PCHUNK, 64>>>(batch);
    k_final<<<GG, 64>>>(ow, ob, out);
}

// round 5
// speedup vs baseline: 1.6786x; 1.0169x over previous
#include <cuda_runtime.h>
#include <math.h>

#define NN   50000
#define EE   800000
#define FIN  32
#define HH   64
#define H2   128
#define EDIM 16
#define GG   64
#define COUT 40
#define PCHUNK 128

typedef unsigned long long u64;
typedef unsigned int u32;

#define FMA2(acc, a, b) asm("fma.rn.f32x2 %0, %1, %2, %0;" : "+l"(acc) : "l"(a), "l"(b))
#define PACK2(d, lo, hi) asm("mov.b64 %0, {%1, %2};" : "=l"(d) : "r"(lo), "r"(hi))
#define UNPACK2(lo, hi, s) asm("mov.b64 {%0, %1}, %2;" : "=r"(lo), "=r"(hi) : "l"(s))

// ---------------- scratch (no allocation allowed) ----------------
__device__ float g_h[NN * HH];      // node features (residual stream)
__device__ float g_z[NN * HH];      // post norm-act features
__device__ float g_agg[NN * HH];    // softmax-agg output + root (MLP1 input)
__device__ float g_hmid[NN * H2];   // MLP hidden
__device__ float g_sA[3][HH];
__device__ float g_qA[3][HH];
__device__ float g_sB[2][H2];
__device__ float g_qB[2][H2];
__device__ float g_pool[GG * HH];
__device__ float g_cnt[GG];
// CSR scratch
__device__ int g_deg[NN];
__device__ int g_cur[NN];
__device__ int g_off[NN + 1];
__device__ int2 g_pe[EE];           // {src, eid}
__device__ int g_bsum[64];
__device__ int g_bbase[64];

// ---------------- zero all accumulators ----------------
__global__ void k_zero() {
    int i = blockIdx.x * blockDim.x + threadIdx.x;
    if (i < NN) { g_deg[i] = 0; g_cur[i] = 0; }
    if (i < 3 * HH) { ((float*)g_sA)[i] = 0.f; ((float*)g_qA)[i] = 0.f; }
    if (i < 2 * H2) { ((float*)g_sB)[i] = 0.f; ((float*)g_qB)[i] = 0.f; }
    if (i < GG * HH) g_pool[i] = 0.f;
    if (i < GG) g_cnt[i] = 0.f;
}

// -------- input linear: h = x @ W_in + b, fused statsA(0) epilogue --------
__global__ void k_lin_in(const float* __restrict__ x,
                         const float* __restrict__ W,
                         const float* __restrict__ b) {
    __shared__ float Wsh[FIN * HH];       // 8KB
    __shared__ float xs[16][FIN + 1];
    __shared__ float red[4][HH];
    int tid = threadIdx.x;
    int j = tid & 63, ig = tid >> 6;      // ig: 0..3

    for (int i = tid; i < FIN * HH; i += 256) Wsh[i] = W[i];
    int n0 = blockIdx.x * 16;             // 3125 blocks * 16 = 50000 exactly
    for (int i = tid; i < 16 * FIN; i += 256) {
        int nl = i >> 5, k = i & 31;
        xs[nl][k] = x[(n0 + nl) * FIN + k];
    }
    __syncthreads();

    float bj = b[j];
    float acc[4];
#pragma unroll
    for (int r = 0; r < 4; r++) acc[r] = bj;
#pragma unroll
    for (int k = 0; k < FIN; k++) {
        float wv = Wsh[k * HH + j];
#pragma unroll
        for (int r = 0; r < 4; r++) acc[r] += xs[ig * 4 + r][k] * wv;
    }
    float s = 0.f, q = 0.f;
#pragma unroll
    for (int r = 0; r < 4; r++) {
        g_h[(n0 + ig * 4 + r) * HH + j] = acc[r];
        s += acc[r]; q += acc[r] * acc[r];
    }
    red[ig][j] = s;
    __syncthreads();
    if (ig == 0) {
        float S = red[0][j] + red[1][j] + red[2][j] + red[3][j];
        atomicAdd(&g_sA[0][j], S);
    }
    __syncthreads();
    red[ig][j] = q;
    __syncthreads();
    if (ig == 0) {
        float Q = red[0][j] + red[1][j] + red[2][j] + red[3][j];
        atomicAdd(&g_qA[0][j], Q);
    }
}

// ---------------- CSR build ----------------
__global__ void k_hist(const int* __restrict__ ei) {
    int t = blockIdx.x * blockDim.x + threadIdx.x;
    if (t * 4 >= EE) return;
    int4 d4 = ((const int4*)(ei + EE))[t];
    atomicAdd(&g_deg[d4.x], 1);
    atomicAdd(&g_deg[d4.y], 1);
    atomicAdd(&g_deg[d4.z], 1);
    atomicAdd(&g_deg[d4.w], 1);
}

__global__ void k_scanA() {
    __shared__ int sh[1024];
    int t = threadIdx.x;
    int i = blockIdx.x * 1024 + t;
    int v = (i < NN) ? g_deg[i] : 0;
    sh[t] = v;
    __syncthreads();
    for (int off = 1; off < 1024; off <<= 1) {
        int u = (t >= off) ? sh[t - off] : 0;
        __syncthreads();
        sh[t] += u;
        __syncthreads();
    }
    if (i < NN) g_off[i] = sh[t] - v;   // exclusive (local)
    if (t == 1023) g_bsum[blockIdx.x] = sh[t];
}

__global__ void k_scanB(int nblk) {
    __shared__ int sh[64];
    int t = threadIdx.x;
    int v = (t < nblk) ? g_bsum[t] : 0;
    sh[t] = v;
    __syncthreads();
    for (int off = 1; off < 64; off <<= 1) {
        int u = (t >= off) ? sh[t - off] : 0;
        __syncthreads();
        sh[t] += u;
        __syncthreads();
    }
    if (t < nblk) g_bbase[t] = sh[t] - v;
}

__global__ void k_scanC() {
    int i = blockIdx.x * 1024 + threadIdx.x;
    if (i < NN) g_off[i] += g_bbase[blockIdx.x];
    if (i == 0) g_off[NN] = EE;
}

__global__ void k_scatter(const int* __restrict__ ei) {
    int t = blockIdx.x * blockDim.x + threadIdx.x;
    if (t * 4 >= EE) return;
    int4 s4 = ((const int4*)ei)[t];
    int4 d4 = ((const int4*)(ei + EE))[t];
    int e0 = t * 4;
    int p, d;
    d = d4.x; p = atomicAdd(&g_cur[d], 1); g_pe[g_off[d] + p] = make_int2(s4.x, e0);
    d = d4.y; p = atomicAdd(&g_cur[d], 1); g_pe[g_off[d] + p] = make_int2(s4.y, e0 + 1);
    d = d4.z; p = atomicAdd(&g_cur[d], 1); g_pe[g_off[d] + p] = make_int2(s4.z, e0 + 2);
    d = d4.w; p = atomicAdd(&g_cur[d], 1); g_pe[g_off[d] + p] = make_int2(s4.w, e0 + 3);
}

// ------- z = relu(BN(h)), float4 vectorized ----------
__global__ void k_bnrelu(const float* __restrict__ gamma,
                         const float* __restrict__ beta, int l) {
    __shared__ float sc[HH], sf[HH];
    int tid = threadIdx.x;
    if (tid < HH) {
        float mu = g_sA[l][tid] * (1.f / NN);
        float var = g_qA[l][tid] * (1.f / NN) - mu * mu;
        float rs = rsqrtf(var + 1e-5f);
        float s = gamma[tid] * rs;
        sc[tid] = s;
        sf[tid] = beta[tid] - mu * s;
    }
    __syncthreads();
    int total = NN * HH / 4;
    for (int i = blockIdx.x * blockDim.x + tid; i < total; i += gridDim.x * blockDim.x) {
        int j = (i * 4) & 63;
        float4 v = ((const float4*)g_h)[i];
        float4 o;
        o.x = fmaxf(v.x * sc[j]     + sf[j],     0.f);
        o.y = fmaxf(v.y * sc[j + 1] + sf[j + 1], 0.f);
        o.z = fmaxf(v.z * sc[j + 2] + sf[j + 2], 0.f);
        o.w = fmaxf(v.w * sc[j + 3] + sf[j + 3], 0.f);
        ((float4*)g_z)[i] = o;
    }
}

// ------- CSR-gather: edge-MLP + message + softmax-agg + root add -------
__global__ void k_gather(const float* __restrict__ ea,
                         const float* __restrict__ W,
                         const float* __restrict__ b,
                         const float* __restrict__ tptr) {
    int warp = (blockIdx.x * blockDim.x + threadIdx.x) >> 5;
    int lane = threadIdx.x & 31;
    if (warp >= NN) return;
    int n = warp;
    float tc = tptr[0];
    int j0 = lane, j1 = lane + 32;
    float W0[EDIM], W1[EDIM];
#pragma unroll
    for (int k = 0; k < EDIM; k++) { W0[k] = W[k * HH + j0]; W1[k] = W[k * HH + j1]; }
    float b0 = b[j0], b1 = b[j1];
    int beg = g_off[n], end = g_off[n + 1];
    float den0 = 0.f, num0 = 0.f, den1 = 0.f, num1 = 0.f;
#pragma unroll 2
    for (int i = beg; i < end; i++) {
        int2 pe = g_pe[i];
        int src = pe.x, eid = pe.y;
        const float4* eav4 = (const float4*)(ea + (size_t)eid * EDIM);
        float eav[EDIM];
        *(float4*)&eav[0]  = eav4[0];
        *(float4*)&eav[4]  = eav4[1];
        *(float4*)&eav[8]  = eav4[2];
        *(float4*)&eav[12] = eav4[3];
        float z0 = g_z[src * HH + j0];
        float z1 = g_z[src * HH + j1];
        float emb0 = b0, emb1 = b1;
#pragma unroll
        for (int k = 0; k < EDIM; k++) { emb0 += eav[k] * W0[k]; emb1 += eav[k] * W1[k]; }
        float m0 = fmaxf(z0 + emb0, 0.f) + 1e-7f;
        float m1 = fmaxf(z1 + emb1, 0.f) + 1e-7f;
        float ex0 = __expf(m0 * tc);   // no max-shift: m in [1e-7, ~6], no overflow
        float ex1 = __expf(m1 * tc);
        den0 += ex0; num0 += ex0 * m0;
        den1 += ex1; num1 += ex1 * m1;
    }
    g_agg[n * HH + j0] = num0 / (den0 + 1e-16f) + g_z[n * HH + j0];
    g_agg[n * HH + j1] = num1 / (den1 + 1e-16f) + g_z[n * HH + j1];
}

// ------- MLP1 GEMM, f32x2 packed: g_hmid[N,128] = g_agg[N,64] @ w1 + b1 -----
// As transposed [k][n] (pad 66); 256 thr; each: 4 node-pairs x 4 cols packed
__global__ void k_mlp1(const float* __restrict__ w1, const float* __restrict__ b1, int l) {
    __shared__ float As[64 * 66];       // 16.9KB transposed
    __shared__ float sred[8][H2];       // 4KB
    int tid = threadIdx.x;  // 256
    int n0 = blockIdx.x * 64;
    {
        int k = tid & 63, ng = tid >> 6;
#pragma unroll
        for (int r = 0; r < 16; r++) {
            int n = ng * 16 + r;
            int gn = n0 + n;
            As[k * 66 + n] = (gn < NN) ? g_agg[gn * HH + k] : 0.f;
        }
    }
    __syncthreads();
    int tx = tid & 31, ty = tid >> 5;
    int col = tx * 4, row0 = ty * 8;
    u64 acc[4][4];
#pragma unroll
    for (int rp = 0; rp < 4; rp++)
#pragma unroll
        for (int c = 0; c < 4; c++) acc[rp][c] = 0ull;
#pragma unroll 4
    for (int k = 0; k < 64; k++) {
        u64 ap[4];
#pragma unroll
        for (int rp = 0; rp < 4; rp++)
            ap[rp] = *(const u64*)&As[k * 66 + row0 + rp * 2];
        float4 wv = *(const float4*)&w1[k * H2 + col];
#pragma unroll
        for (int c = 0; c < 4; c++) {
            u32 wb = __float_as_uint(((const float*)&wv)[c]);
            u64 wd; PACK2(wd, wb, wb);
#pragma unroll
            for (int rp = 0; rp < 4; rp++) FMA2(acc[rp][c], ap[rp], wd);
        }
    }
    float4 bb = *(const float4*)&b1[col];
    float s[4] = {0.f, 0.f, 0.f, 0.f}, q[4] = {0.f, 0.f, 0.f, 0.f};
#pragma unroll
    for (int rp = 0; rp < 4; rp++) {
        float o0[4], o1[4];
#pragma unroll
        for (int c = 0; c < 4; c++) {
            u32 lo, hi; UNPACK2(lo, hi, acc[rp][c]);
            o0[c] = __uint_as_float(lo) + ((const float*)&bb)[c];
            o1[c] = __uint_as_float(hi) + ((const float*)&bb)[c];
        }
        int na = n0 + row0 + rp * 2;
        if (na < NN) {
            *(float4*)&g_hmid[na * H2 + col] = make_float4(o0[0], o0[1], o0[2], o0[3]);
#pragma unroll
            for (int c = 0; c < 4; c++) { s[c] += o0[c]; q[c] += o0[c] * o0[c]; }
        }
        if (na + 1 < NN) {
            *(float4*)&g_hmid[(na + 1) * H2 + col] = make_float4(o1[0], o1[1], o1[2], o1[3]);
#pragma unroll
            for (int c = 0; c < 4; c++) { s[c] += o1[c]; q[c] += o1[c] * o1[c]; }
        }
    }
#pragma unroll
    for (int c = 0; c < 4; c++) sred[ty][col + c] = s[c];
    __syncthreads();
    if (tid < H2) {
        float S = 0.f;
#pragma unroll
        for (int i = 0; i < 8; i++) S += sred[i][tid];
        atomicAdd(&g_sB[l][tid], S);
    }
    __syncthreads();
#pragma unroll
    for (int c = 0; c < 4; c++) sred[ty][col + c] = q[c];
    __syncthreads();
    if (tid < H2) {
        float Q = 0.f;
#pragma unroll
        for (int i = 0; i < 8; i++) Q += sred[i][tid];
        atomicAdd(&g_qB[l][tid], Q);
    }
}

// ------- MLP2 GEMM, f32x2 packed, fused BN2+ReLU staging + residual --------
// g_h[N,64] += relu(BN(g_hmid)) @ w2 + b2 ; As transposed [k=128][n=64] pad 66
__global__ void k_mlp2(const float* __restrict__ w2, const float* __restrict__ b2,
                       const float* __restrict__ gamma, const float* __restrict__ beta,
                       int l) {
    __shared__ float As[H2 * 66];       // 33.8KB
    __shared__ float sred[8][HH];       // 2KB
    int tid = threadIdx.x;  // 128
    int n0 = blockIdx.x * 64;
    {   // tid == k row; BN params in registers
        float mu = g_sB[l][tid] * (1.f / NN);
        float var = g_qB[l][tid] * (1.f / NN) - mu * mu;
        float rs = rsqrtf(var + 1e-5f);
        float scr = gamma[tid] * rs;
        float sfr = beta[tid] - mu * scr;
#pragma unroll 4
        for (int n = 0; n < 64; n++) {
            int gn = n0 + n;
            float v = (gn < NN) ? g_hmid[gn * H2 + tid] : 0.f;
            As[tid * 66 + n] = fmaxf(v * scr + sfr, 0.f);
        }
    }
    __syncthreads();
    int tx = tid & 15, ty = tid >> 4;
    int col = tx * 4, row0 = ty * 8;
    u64 acc[4][4];
#pragma unroll
    for (int rp = 0; rp < 4; rp++)
#pragma unroll
        for (int c = 0; c < 4; c++) acc[rp][c] = 0ull;
#pragma unroll 4
    for (int k = 0; k < H2; k++) {
        u64 ap[4];
#pragma unroll
        for (int rp = 0; rp < 4; rp++)
            ap[rp] = *(const u64*)&As[k * 66 + row0 + rp * 2];
        float4 wv = *(const float4*)&w2[k * HH + col];
#pragma unroll
        for (int c = 0; c < 4; c++) {
            u32 wb = __float_as_uint(((const float*)&wv)[c]);
            u64 wd; PACK2(wd, wb, wb);
#pragma unroll
            for (int rp = 0; rp < 4; rp++) FMA2(acc[rp][c], ap[rp], wd);
        }
    }
    float4 bb = *(const float4*)&b2[col];
    float s[4] = {0.f, 0.f, 0.f, 0.f}, q[4] = {0.f, 0.f, 0.f, 0.f};
#pragma unroll
    for (int rp = 0; rp < 4; rp++) {
        float o0[4], o1[4];
#pragma unroll
        for (int c = 0; c < 4; c++) {
            u32 lo, hi; UNPACK2(lo, hi, acc[rp][c]);
            o0[c] = __uint_as_float(lo) + ((const float*)&bb)[c];
            o1[c] = __uint_as_float(hi) + ((const float*)&bb)[c];
        }
        int na = n0 + row0 + rp * 2;
        if (na < NN) {
            float4 h = *(const float4*)&g_h[na * HH + col];
            h.x += o0[0]; h.y += o0[1]; h.z += o0[2]; h.w += o0[3];
            *(float4*)&g_h[na * HH + col] = h;
            s[0] += h.x; s[1] += h.y; s[2] += h.z; s[3] += h.w;
            q[0] += h.x * h.x; q[1] += h.y * h.y; q[2] += h.z * h.z; q[3] += h.w * h.w;
        }
        if (na + 1 < NN) {
            float4 h = *(const float4*)&g_h[(na + 1) * HH + col];
            h.x += o1[0]; h.y += o1[1]; h.z += o1[2]; h.w += o1[3];
            *(float4*)&g_h[(na + 1) * HH + col] = h;
            s[0] += h.x; s[1] += h.y; s[2] += h.z; s[3] += h.w;
            q[0] += h.x * h.x; q[1] += h.y * h.y; q[2] += h.z * h.z; q[3] += h.w * h.w;
        }
    }
#pragma unroll
    for (int c = 0; c < 4; c++) sred[ty][col + c] = s[c];
    __syncthreads();
    if (tid < HH) {
        float S = 0.f;
#pragma unroll
        for (int i = 0; i < 8; i++) S += sred[i][tid];
        atomicAdd(&g_sA[l + 1][tid], S);
    }
    __syncthreads();
#pragma unroll
    for (int c = 0; c < 4; c++) sred[ty][col + c] = q[c];
    __syncthreads();
    if (tid < HH) {
        float Q = 0.f;
#pragma unroll
        for (int i = 0; i < 8; i++) Q += sred[i][tid];
        atomicAdd(&g_qA[l + 1][tid], Q);
    }
}

// ------- global mean pool (batch is sorted): block-chunked segment sum -------
__global__ void k_pool(const int* __restrict__ batch) {
    int j = threadIdx.x;  // 64
    int n0 = blockIdx.x * PCHUNK;
    if (n0 >= NN) return;
    int n1 = min(n0 + PCHUNK, NN);
    int cur = batch[n0];
    float s = 0.f, cnt = 0.f;
    for (int n = n0; n < n1; n++) {
        int b = batch[n];
        if (b != cur) {
            atomicAdd(&g_pool[cur * HH + j], s);
            if (j == 0) atomicAdd(&g_cnt[cur], cnt);
            s = 0.f; cnt = 0.f; cur = b;
        }
        s += g_h[n * HH + j];
        cnt += 1.f;
    }
    atomicAdd(&g_pool[cur * HH + j], s);
    if (j == 0) atomicAdd(&g_cnt[cur], cnt);
}

// ------- output: out = relu(pooled) @ W_out + b_out -------
__global__ void k_final(const float* __restrict__ W, const float* __restrict__ b,
                        float* __restrict__ out) {
    __shared__ float p[HH];
    int g = blockIdx.x, tid = threadIdx.x;  // 64
    float c = fmaxf(g_cnt[g], 1.f);
    p[tid] = fmaxf(g_pool[g * HH + tid] / c, 0.f);
    __syncthreads();
    if (tid < COUT) {
        float acc = b[tid];
#pragma unroll
        for (int k = 0; k < HH; k++) acc += p[k] * W[k * COUT + tid];
        out[g * COUT + tid] = acc;
    }
}

extern "C" void kernel_launch(void* const* d_in, const int* in_sizes, int n_in,
                              void* d_out, int out_size) {
    const float* x        = (const float*)d_in[0];
    const int*   ei       = (const int*)d_in[1];
    const float* ea       = (const float*)d_in[2];
    const int*   batch    = (const int*)d_in[3];
    const float* lin_in_w = (const float*)d_in[4];
    const float* lin_in_b = (const float*)d_in[5];
    const float* ng       = (const float*)d_in[6];
    const float* nb       = (const float*)d_in[7];
    const float* ew       = (const float*)d_in[8];
    const float* eb       = (const float*)d_in[9];
    const float* tt       = (const float*)d_in[10];
    const float* w1       = (const float*)d_in[11];
    const float* b1       = (const float*)d_in[12];
    const float* mg       = (const float*)d_in[13];
    const float* mb       = (const float*)d_in[14];
    const float* w2       = (const float*)d_in[15];
    const float* b2       = (const float*)d_in[16];
    const float* ow       = (const float*)d_in[17];
    const float* ob       = (const float*)d_in[18];
    float* out = (float*)d_out;

    const int SCAN_BLKS = (NN + 1023) / 1024;   // 49

    k_zero<<<(NN + 511) / 512, 512>>>();
    k_hist<<<(EE / 4 + 255) / 256, 256>>>(ei);
    k_scanA<<<SCAN_BLKS, 1024>>>();
    k_scanB<<<1, 64>>>(SCAN_BLKS);
    k_scanC<<<SCAN_BLKS, 1024>>>();
    k_scatter<<<(EE / 4 + 255) / 256, 256>>>(ei);   // 6th launch -> profiled
    k_lin_in<<<NN / 16, 256>>>(x, lin_in_w, lin_in_b);
    for (int l = 0; l < 2; l++) {
        k_bnrelu<<<1024, 256>>>(ng + l * HH, nb + l * HH, l);
        k_gather<<<(NN * 32 + 255) / 256, 256>>>(ea, ew + l * EDIM * HH, eb + l * HH, tt + l);
        k_mlp1<<<(NN + 63) / 64, 256>>>(w1 + l * HH * H2, b1 + l * H2, l);
        k_mlp2<<<(NN + 63) / 64, 128>>>(w2 + l * H2 * HH, b2 + l * HH,
                                        mg + l * H2, mb + l * H2, l);
    }
    k_pool<<<(NN + PCHUNK - 1) / PCHUNK, 64>>>(batch);
    k_final<<<GG, 64>>>(ow, ob, out);
}

// round 6
// speedup vs baseline: 1.7672x; 1.0527x over previous
#include <cuda_runtime.h>
#include <math.h>

#define NN   50000
#define EE   800000
#define FIN  32
#define HH   64
#define H2   128
#define EDIM 16
#define GG   64
#define COUT 40
#define PCHUNK 128

typedef unsigned long long u64;
typedef unsigned int u32;

#define FMA2(acc, a, b) asm("fma.rn.f32x2 %0, %1, %2, %0;" : "+l"(acc) : "l"(a), "l"(b))
#define FMA2D(d, a, b, c) asm("fma.rn.f32x2 %0, %1, %2, %3;" : "=l"(d) : "l"(a), "l"(b), "l"(c))
#define PACK2(d, lo, hi) asm("mov.b64 %0, {%1, %2};" : "=l"(d) : "r"(lo), "r"(hi))
#define UNPACK2(lo, hi, s) asm("mov.b64 {%0, %1}, %2;" : "=r"(lo), "=r"(hi) : "l"(s))

// ---------------- scratch (no allocation allowed) ----------------
__device__ float g_h[NN * HH];      // node features (residual stream)
__device__ float g_agg[NN * HH];    // softmax-agg output + root (MLP1 input)
__device__ float g_hmid[NN * H2];   // MLP hidden
__device__ float g_sA[3][HH];
__device__ float g_qA[3][HH];
__device__ float g_sB[2][H2];
__device__ float g_qB[2][H2];
__device__ float g_pool[GG * HH];
__device__ float g_cnt[GG];
// CSR scratch
__device__ int g_deg[NN];
__device__ int g_cur[NN];
__device__ int g_off[NN + 1];
__device__ int g_psrc[EE];
__device__ float g_eac[(size_t)EE * EDIM];   // edge_attr in CSR order
__device__ u64 g_look[64];

// ---------------- zero all accumulators ----------------
__global__ void k_zero() {
    int i = blockIdx.x * blockDim.x + threadIdx.x;
    if (i < NN) { g_deg[i] = 0; g_cur[i] = 0; }
    if (i < 3 * HH) { ((float*)g_sA)[i] = 0.f; ((float*)g_qA)[i] = 0.f; }
    if (i < 2 * H2) { ((float*)g_sB)[i] = 0.f; ((float*)g_qB)[i] = 0.f; }
    if (i < GG * HH) g_pool[i] = 0.f;
    if (i < GG) g_cnt[i] = 0.f;
    if (i < 64) g_look[i] = 0ull;
}

// -------- input linear: h = x @ W_in + b, fused statsA(0) epilogue --------
__global__ void k_lin_in(const float* __restrict__ x,
                         const float* __restrict__ W,
                         const float* __restrict__ b) {
    __shared__ float Wsh[FIN * HH];       // 8KB
    __shared__ float xs[16][FIN + 1];
    __shared__ float red[4][HH];
    int tid = threadIdx.x;
    int j = tid & 63, ig = tid >> 6;      // ig: 0..3

    for (int i = tid; i < FIN * HH; i += 256) Wsh[i] = W[i];
    int n0 = blockIdx.x * 16;             // 3125 blocks * 16 = 50000 exactly
    for (int i = tid; i < 16 * FIN; i += 256) {
        int nl = i >> 5, k = i & 31;
        xs[nl][k] = x[(n0 + nl) * FIN + k];
    }
    __syncthreads();

    float bj = b[j];
    float acc[4];
#pragma unroll
    for (int r = 0; r < 4; r++) acc[r] = bj;
#pragma unroll
    for (int k = 0; k < FIN; k++) {
        float wv = Wsh[k * HH + j];
#pragma unroll
        for (int r = 0; r < 4; r++) acc[r] += xs[ig * 4 + r][k] * wv;
    }
    float s = 0.f, q = 0.f;
#pragma unroll
    for (int r = 0; r < 4; r++) {
        g_h[(n0 + ig * 4 + r) * HH + j] = acc[r];
        s += acc[r]; q += acc[r] * acc[r];
    }
    red[ig][j] = s;
    __syncthreads();
    if (ig == 0) {
        float S = red[0][j] + red[1][j] + red[2][j] + red[3][j];
        atomicAdd(&g_sA[0][j], S);
    }
    __syncthreads();
    red[ig][j] = q;
    __syncthreads();
    if (ig == 0) {
        float Q = red[0][j] + red[1][j] + red[2][j] + red[3][j];
        atomicAdd(&g_qA[0][j], Q);
    }
}

// ---------------- CSR build ----------------
__global__ void k_hist(const int* __restrict__ ei) {
    int t = blockIdx.x * blockDim.x + threadIdx.x;
    if (t * 4 >= EE) return;
    int4 d4 = ((const int4*)(ei + EE))[t];
    atomicAdd(&g_deg[d4.x], 1);
    atomicAdd(&g_deg[d4.y], 1);
    atomicAdd(&g_deg[d4.z], 1);
    atomicAdd(&g_deg[d4.w], 1);
}

// single-kernel scan with decoupled lookback (49 blocks, all resident wave 1)
__global__ void k_scan() {
    __shared__ int sh[1024];
    __shared__ int exc_sh;
    int b = blockIdx.x, t = threadIdx.x;
    int i = b * 1024 + t;
    int v = (i < NN) ? g_deg[i] : 0;
    sh[t] = v;
    __syncthreads();
    for (int off = 1; off < 1024; off <<= 1) {
        int u = (t >= off) ? sh[t - off] : 0;
        __syncthreads();
        sh[t] += u;
        __syncthreads();
    }
    int total = sh[1023];
    if (t == 0) {
        const u64 FA = 1ull << 62, FP = 2ull << 62;
        if (b == 0) {
            atomicExch(&g_look[0], FP | (u32)total);
            exc_sh = 0;
        } else {
            atomicExch(&g_look[b], FA | (u32)total);
            int run = 0, j = b - 1;
            while (1) {
                u64 s = atomicAdd(&g_look[j], 0ull);
                u64 f = s >> 62;
                if (f == 0) continue;
                int val = (int)(s & 0xFFFFFFFFull);
                run += val;
                if (f == 2) break;
                j--;
            }
            atomicExch(&g_look[b], FP | (u32)(run + total));
            exc_sh = run;
        }
    }
    __syncthreads();
    int e = exc_sh;
    if (i < NN) g_off[i] = e + sh[t] - v;   // exclusive
    if (b == 0 && t == 0) g_off[NN] = EE;
}

// scatter: build CSR src list AND copy edge_attr into CSR order
__global__ void k_scatter(const int* __restrict__ ei, const float* __restrict__ ea) {
    int t = blockIdx.x * blockDim.x + threadIdx.x;
    if (t * 4 >= EE) return;
    int4 s4 = ((const int4*)ei)[t];
    int4 d4 = ((const int4*)(ei + EE))[t];
    int e0 = t * 4;
#pragma unroll
    for (int r = 0; r < 4; r++) {
        int src = (r == 0) ? s4.x : (r == 1) ? s4.y : (r == 2) ? s4.z : s4.w;
        int d   = (r == 0) ? d4.x : (r == 1) ? d4.y : (r == 2) ? d4.z : d4.w;
        int p = atomicAdd(&g_cur[d], 1);
        int idx = g_off[d] + p;
        g_psrc[idx] = src;
        const float4* sp = (const float4*)(ea + (size_t)(e0 + r) * EDIM);
        float4* dp = (float4*)(g_eac + (size_t)idx * EDIM);
        dp[0] = sp[0]; dp[1] = sp[1]; dp[2] = sp[2]; dp[3] = sp[3];
    }
}

// ------- CSR-gather: fused BN+ReLU + edge-MLP(f32x2) + softmax-agg + root ---
// one warp per node; lane owns features (2*lane, 2*lane+1)
__global__ void k_gather(const float* __restrict__ W, const float* __restrict__ bb,
                         const float* __restrict__ gamma, const float* __restrict__ beta,
                         const float* __restrict__ tptr, int l) {
    int warp = (blockIdx.x * blockDim.x + threadIdx.x) >> 5;
    int lane = threadIdx.x & 31;
    if (warp >= NN) return;
    int n = warp;
    float tc = tptr[0];
    int j0 = lane * 2;
    // BN constants for the 2 owned features
    float2 sA = *(const float2*)&g_sA[l][j0];
    float2 qA = *(const float2*)&g_qA[l][j0];
    float2 gm = *(const float2*)&gamma[j0];
    float2 bt = *(const float2*)&beta[j0];
    float mu0 = sA.x * (1.f / NN), mu1 = sA.y * (1.f / NN);
    float sc0 = gm.x * rsqrtf(qA.x * (1.f / NN) - mu0 * mu0 + 1e-5f);
    float sc1 = gm.y * rsqrtf(qA.y * (1.f / NN) - mu1 * mu1 + 1e-5f);
    float sf0 = bt.x - mu0 * sc0, sf1 = bt.y - mu1 * sc1;
    u64 scp, sfp;
    PACK2(scp, __float_as_uint(sc0), __float_as_uint(sc1));
    PACK2(sfp, __float_as_uint(sf0), __float_as_uint(sf1));
    // edge-MLP weight k-pairs for both features (packed once per warp)
    u64 w0p[8], w1p[8];
#pragma unroll
    for (int t2 = 0; t2 < 8; t2++) {
        float a0 = W[(2 * t2) * HH + j0],     a1 = W[(2 * t2 + 1) * HH + j0];
        float c0 = W[(2 * t2) * HH + j0 + 1], c1 = W[(2 * t2 + 1) * HH + j0 + 1];
        PACK2(w0p[t2], __float_as_uint(a0), __float_as_uint(a1));
        PACK2(w1p[t2], __float_as_uint(c0), __float_as_uint(c1));
    }
    float b0 = bb[j0], b1 = bb[j0 + 1];
    int beg = g_off[n], end = g_off[n + 1];
    float den0 = 0.f, num0 = 0.f, den1 = 0.f, num1 = 0.f;
#pragma unroll 2
    for (int i = beg; i < end; i++) {
        int src = g_psrc[i];
        const ulonglong2* E2 = (const ulonglong2*)(g_eac + (size_t)i * EDIM);
        ulonglong2 p0 = E2[0], p1 = E2[1], p2 = E2[2], p3 = E2[3];
        u64 acc0 = 0ull, acc1 = 0ull;
        FMA2(acc0, p0.x, w0p[0]); FMA2(acc1, p0.x, w1p[0]);
        FMA2(acc0, p0.y, w0p[1]); FMA2(acc1, p0.y, w1p[1]);
        FMA2(acc0, p1.x, w0p[2]); FMA2(acc1, p1.x, w1p[2]);
        FMA2(acc0, p1.y, w0p[3]); FMA2(acc1, p1.y, w1p[3]);
        FMA2(acc0, p2.x, w0p[4]); FMA2(acc1, p2.x, w1p[4]);
        FMA2(acc0, p2.y, w0p[5]); FMA2(acc1, p2.y, w1p[5]);
        FMA2(acc0, p3.x, w0p[6]); FMA2(acc1, p3.x, w1p[6]);
        FMA2(acc0, p3.y, w0p[7]); FMA2(acc1, p3.y, w1p[7]);
        u32 lo, hi;
        UNPACK2(lo, hi, acc0);
        float emb0 = b0 + __uint_as_float(lo) + __uint_as_float(hi);
        UNPACK2(lo, hi, acc1);
        float emb1 = b1 + __uint_as_float(lo) + __uint_as_float(hi);
        // z = relu(BN(h[src])) computed on the fly
        u64 h2 = *(const u64*)&g_h[src * HH + j0];
        u64 z2; FMA2D(z2, h2, scp, sfp);
        UNPACK2(lo, hi, z2);
        float z0 = fmaxf(__uint_as_float(lo), 0.f);
        float z1 = fmaxf(__uint_as_float(hi), 0.f);
        float m0 = fmaxf(z0 + emb0, 0.f) + 1e-7f;
        float m1 = fmaxf(z1 + emb1, 0.f) + 1e-7f;
        float ex0 = __expf(m0 * tc);   // no max-shift: m in [1e-7, ~6]
        float ex1 = __expf(m1 * tc);
        den0 += ex0; num0 += ex0 * m0;
        den1 += ex1; num1 += ex1 * m1;
    }
    // root term
    u64 h2 = *(const u64*)&g_h[n * HH + j0];
    u64 z2; FMA2D(z2, h2, scp, sfp);
    u32 lo, hi; UNPACK2(lo, hi, z2);
    float zr0 = fmaxf(__uint_as_float(lo), 0.f);
    float zr1 = fmaxf(__uint_as_float(hi), 0.f);
    float a0 = num0 / (den0 + 1e-16f) + zr0;
    float a1 = num1 / (den1 + 1e-16f) + zr1;
    *(float2*)&g_agg[n * HH + j0] = make_float2(a0, a1);
}

// ------- MLP1 GEMM, f32x2 packed: g_hmid[N,128] = g_agg[N,64] @ w1 + b1 -----
__global__ void k_mlp1(const float* __restrict__ w1, const float* __restrict__ b1, int l) {
    __shared__ float As[64 * 66];       // transposed [k][n]
    __shared__ float sred[8][H2];
    int tid = threadIdx.x;  // 256
    int n0 = blockIdx.x * 64;
    for (int idx = tid; idx < 64 * 16; idx += 256) {
        int r = idx >> 4, c4 = (idx & 15) * 4;
        int gn = n0 + r;
        float4 v = (gn < NN) ? *(const float4*)&g_agg[gn * HH + c4]
                             : make_float4(0.f, 0.f, 0.f, 0.f);
        As[(c4 + 0) * 66 + r] = v.x;
        As[(c4 + 1) * 66 + r] = v.y;
        As[(c4 + 2) * 66 + r] = v.z;
        As[(c4 + 3) * 66 + r] = v.w;
    }
    __syncthreads();
    int tx = tid & 31, ty = tid >> 5;
    int col = tx * 4, row0 = ty * 8;
    u64 acc[4][4];
#pragma unroll
    for (int rp = 0; rp < 4; rp++)
#pragma unroll
        for (int c = 0; c < 4; c++) acc[rp][c] = 0ull;
#pragma unroll 4
    for (int k = 0; k < 64; k++) {
        u64 ap[4];
#pragma unroll
        for (int rp = 0; rp < 4; rp++)
            ap[rp] = *(const u64*)&As[k * 66 + row0 + rp * 2];
        float4 wv = *(const float4*)&w1[k * H2 + col];
#pragma unroll
        for (int c = 0; c < 4; c++) {
            u32 wb = __float_as_uint(((const float*)&wv)[c]);
            u64 wd; PACK2(wd, wb, wb);
#pragma unroll
            for (int rp = 0; rp < 4; rp++) FMA2(acc[rp][c], ap[rp], wd);
        }
    }
    float4 bb = *(const float4*)&b1[col];
    float s[4] = {0.f, 0.f, 0.f, 0.f}, q[4] = {0.f, 0.f, 0.f, 0.f};
#pragma unroll
    for (int rp = 0; rp < 4; rp++) {
        float o0[4], o1[4];
#pragma unroll
        for (int c = 0; c < 4; c++) {
            u32 lo, hi; UNPACK2(lo, hi, acc[rp][c]);
            o0[c] = __uint_as_float(lo) + ((const float*)&bb)[c];
            o1[c] = __uint_as_float(hi) + ((const float*)&bb)[c];
        }
        int na = n0 + row0 + rp * 2;
        if (na < NN) {
            *(float4*)&g_hmid[na * H2 + col] = make_float4(o0[0], o0[1], o0[2], o0[3]);
#pragma unroll
            for (int c = 0; c < 4; c++) { s[c] += o0[c]; q[c] += o0[c] * o0[c]; }
        }
        if (na + 1 < NN) {
            *(float4*)&g_hmid[(na + 1) * H2 + col] = make_float4(o1[0], o1[1], o1[2], o1[3]);
#pragma unroll
            for (int c = 0; c < 4; c++) { s[c] += o1[c]; q[c] += o1[c] * o1[c]; }
        }
    }
#pragma unroll
    for (int c = 0; c < 4; c++) sred[ty][col + c] = s[c];
    __syncthreads();
    if (tid < H2) {
        float S = 0.f;
#pragma unroll
        for (int i = 0; i < 8; i++) S += sred[i][tid];
        atomicAdd(&g_sB[l][tid], S);
    }
    __syncthreads();
#pragma unroll
    for (int c = 0; c < 4; c++) sred[ty][col + c] = q[c];
    __syncthreads();
    if (tid < H2) {
        float Q = 0.f;
#pragma unroll
        for (int i = 0; i < 8; i++) Q += sred[i][tid];
        atomicAdd(&g_qB[l][tid], Q);
    }
}

// ------- MLP2 GEMM, f32x2 packed, fused BN2+ReLU staging + residual --------
__global__ void k_mlp2(const float* __restrict__ w2, const float* __restrict__ b2,
                       const float* __restrict__ gamma, const float* __restrict__ beta,
                       int l) {
    __shared__ float As[H2 * 66];       // transposed [k][n]
    __shared__ float scs[H2], sfs[H2];
    __shared__ float sred[8][HH];
    int tid = threadIdx.x;  // 128
    int n0 = blockIdx.x * 64;
    {   // tid == k
        float mu = g_sB[l][tid] * (1.f / NN);
        float var = g_qB[l][tid] * (1.f / NN) - mu * mu;
        float scr = gamma[tid] * rsqrtf(var + 1e-5f);
        scs[tid] = scr;
        sfs[tid] = beta[tid] - mu * scr;
    }
    __syncthreads();
    for (int idx = tid; idx < 64 * 32; idx += 128) {
        int r = idx >> 5, c4 = (idx & 31) * 4;
        int gn = n0 + r;
        float4 v = (gn < NN) ? *(const float4*)&g_hmid[gn * H2 + c4]
                             : make_float4(0.f, 0.f, 0.f, 0.f);
        As[(c4 + 0) * 66 + r] = fmaxf(v.x * scs[c4]     + sfs[c4],     0.f);
        As[(c4 + 1) * 66 + r] = fmaxf(v.y * scs[c4 + 1] + sfs[c4 + 1], 0.f);
        As[(c4 + 2) * 66 + r] = fmaxf(v.z * scs[c4 + 2] + sfs[c4 + 2], 0.f);
        As[(c4 + 3) * 66 + r] = fmaxf(v.w * scs[c4 + 3] + sfs[c4 + 3], 0.f);
    }
    __syncthreads();
    int tx = tid & 15, ty = tid >> 4;
    int col = tx * 4, row0 = ty * 8;
    u64 acc[4][4];
#pragma unroll
    for (int rp = 0; rp < 4; rp++)
#pragma unroll
        for (int c = 0; c < 4; c++) acc[rp][c] = 0ull;
#pragma unroll 4
    for (int k = 0; k < H2; k++) {
        u64 ap[4];
#pragma unroll
        for (int rp = 0; rp < 4; rp++)
            ap[rp] = *(const u64*)&As[k * 66 + row0 + rp * 2];
        float4 wv = *(const float4*)&w2[k * HH + col];
#pragma unroll
        for (int c = 0; c < 4; c++) {
            u32 wb = __float_as_uint(((const float*)&wv)[c]);
            u64 wd; PACK2(wd, wb, wb);
#pragma unroll
            for (int rp = 0; rp < 4; rp++) FMA2(acc[rp][c], ap[rp], wd);
        }
    }
    float4 bb = *(const float4*)&b2[col];
    float s[4] = {0.f, 0.f, 0.f, 0.f}, q[4] = {0.f, 0.f, 0.f, 0.f};
#pragma unroll
    for (int rp = 0; rp < 4; rp++) {
        float o0[4], o1[4];
#pragma unroll
        for (int c = 0; c < 4; c++) {
            u32 lo, hi; UNPACK2(lo, hi, acc[rp][c]);
            o0[c] = __uint_as_float(lo) + ((const float*)&bb)[c];
            o1[c] = __uint_as_float(hi) + ((const float*)&bb)[c];
        }
        int na = n0 + row0 + rp * 2;
        if (na < NN) {
            float4 h = *(const float4*)&g_h[na * HH + col];
            h.x += o0[0]; h.y += o0[1]; h.z += o0[2]; h.w += o0[3];
            *(float4*)&g_h[na * HH + col] = h;
            s[0] += h.x; s[1] += h.y; s[2] += h.z; s[3] += h.w;
            q[0] += h.x * h.x; q[1] += h.y * h.y; q[2] += h.z * h.z; q[3] += h.w * h.w;
        }
        if (na + 1 < NN) {
            float4 h = *(const float4*)&g_h[(na + 1) * HH + col];
            h.x += o1[0]; h.y += o1[1]; h.z += o1[2]; h.w += o1[3];
            *(float4*)&g_h[(na + 1) * HH + col] = h;
            s[0] += h.x; s[1] += h.y; s[2] += h.z; s[3] += h.w;
            q[0] += h.x * h.x; q[1] += h.y * h.y; q[2] += h.z * h.z; q[3] += h.w * h.w;
        }
    }
#pragma unroll
    for (int c = 0; c < 4; c++) sred[ty][col + c] = s[c];
    __syncthreads();
    if (tid < HH) {
        float S = 0.f;
#pragma unroll
        for (int i = 0; i < 8; i++) S += sred[i][tid];
        atomicAdd(&g_sA[l + 1][tid], S);
    }
    __syncthreads();
#pragma unroll
    for (int c = 0; c < 4; c++) sred[ty][col + c] = q[c];
    __syncthreads();
    if (tid < HH) {
        float Q = 0.f;
#pragma unroll
        for (int i = 0; i < 8; i++) Q += sred[i][tid];
        atomicAdd(&g_qA[l + 1][tid], Q);
    }
}

// ------- global mean pool (batch is sorted): block-chunked segment sum -------
__global__ void k_pool(const int* __restrict__ batch) {
    int j = threadIdx.x;  // 64
    int n0 = blockIdx.x * PCHUNK;
    if (n0 >= NN) return;
    int n1 = min(n0 + PCHUNK, NN);
    int cur = batch[n0];
    float s = 0.f, cnt = 0.f;
    for (int n = n0; n < n1; n++) {
        int b = batch[n];
        if (b != cur) {
            atomicAdd(&g_pool[cur * HH + j], s);
            if (j == 0) atomicAdd(&g_cnt[cur], cnt);
            s = 0.f; cnt = 0.f; cur = b;
        }
        s += g_h[n * HH + j];
        cnt += 1.f;
    }
    atomicAdd(&g_pool[cur * HH + j], s);
    if (j == 0) atomicAdd(&g_cnt[cur], cnt);
}

// ------- output: out = relu(pooled) @ W_out + b_out -------
__global__ void k_final(const float* __restrict__ W, const float* __restrict__ b,
                        float* __restrict__ out) {
    __shared__ float p[HH];
    int g = blockIdx.x, tid = threadIdx.x;  // 64
    float c = fmaxf(g_cnt[g], 1.f);
    p[tid] = fmaxf(g_pool[g * HH + tid] / c, 0.f);
    __syncthreads();
    if (tid < COUT) {
        float acc = b[tid];
#pragma unroll
        for (int k = 0; k < HH; k++) acc += p[k] * W[k * COUT + tid];
        out[g * COUT + tid] = acc;
    }
}

extern "C" void kernel_launch(void* const* d_in, const int* in_sizes, int n_in,
                              void* d_out, int out_size) {
    const float* x        = (const float*)d_in[0];
    const int*   ei       = (const int*)d_in[1];
    const float* ea       = (const float*)d_in[2];
    const int*   batch    = (const int*)d_in[3];
    const float* lin_in_w = (const float*)d_in[4];
    const float* lin_in_b = (const float*)d_in[5];
    const float* ng       = (const float*)d_in[6];
    const float* nb       = (const float*)d_in[7];
    const float* ew       = (const float*)d_in[8];
    const float* eb       = (const float*)d_in[9];
    const float* tt       = (const float*)d_in[10];
    const float* w1       = (const float*)d_in[11];
    const float* b1       = (const float*)d_in[12];
    const float* mg       = (const float*)d_in[13];
    const float* mb       = (const float*)d_in[14];
    const float* w2       = (const float*)d_in[15];
    const float* b2       = (const float*)d_in[16];
    const float* ow       = (const float*)d_in[17];
    const float* ob       = (const float*)d_in[18];
    float* out = (float*)d_out;

    const int SCAN_BLKS = (NN + 1023) / 1024;   // 49

    k_zero<<<(NN + 511) / 512, 512>>>();
    k_hist<<<(EE / 4 + 255) / 256, 256>>>(ei);
    k_scan<<<SCAN_BLKS, 1024>>>();
    k_scatter<<<(EE / 4 + 255) / 256, 256>>>(ei, ea);
    k_lin_in<<<NN / 16, 256>>>(x, lin_in_w, lin_in_b);
    for (int l = 0; l < 2; l++) {
        k_gather<<<(NN * 32 + 255) / 256, 256>>>(ew + l * EDIM * HH, eb + l * HH,
                                                 ng + l * HH, nb + l * HH, tt + l, l);
        k_mlp1<<<(NN + 63) / 64, 256>>>(w1 + l * HH * H2, b1 + l * H2, l);
        k_mlp2<<<(NN + 63) / 64, 128>>>(w2 + l * H2 * HH, b2 + l * HH,
                                        mg + l * H2, mb + l * H2, l);
    }
    k_pool<<<(NN + PCHUNK - 1) / PCHUNK, 64>>>(batch);
    k_final<<<GG, 64>>>(ow, ob, out);
}

// round 7
// speedup vs baseline: 1.8662x; 1.0561x over previous
#include <cuda_runtime.h>
#include <math.h>

#define NN   50000
#define EE   800000
#define FIN  32
#define HH   64
#define H2   128
#define EDIM 16
#define GG   64
#define COUT 40
#define PCHUNK 64
#define HIST_BLKS 782
#define LIN_BLKS 3125

typedef unsigned long long u64;
typedef unsigned int u32;

#define FMA2(acc, a, b) asm("fma.rn.f32x2 %0, %1, %2, %0;" : "+l"(acc) : "l"(a), "l"(b))
#define FMA2D(d, a, b, c) asm("fma.rn.f32x2 %0, %1, %2, %3;" : "=l"(d) : "l"(a), "l"(b), "l"(c))
#define PACK2(d, lo, hi) asm("mov.b64 %0, {%1, %2};" : "=l"(d) : "r"(lo), "r"(hi))
#define UNPACK2(lo, hi, s) asm("mov.b64 {%0, %1}, %2;" : "=r"(lo), "=r"(hi) : "l"(s))

// ---------------- scratch (no allocation allowed) ----------------
__device__ float g_h[NN * HH];      // node features (residual stream)
__device__ float g_agg[NN * HH];    // softmax-agg output + root (MLP1 input)
__device__ float g_hmid[NN * H2];   // MLP hidden
__device__ float g_sA[3][HH];
__device__ float g_qA[3][HH];
__device__ float g_sB[2][H2];
__device__ float g_qB[2][H2];
__device__ float g_pool[GG * HH];
__device__ float g_cnt[GG];
// CSR scratch
__device__ int g_deg[NN];
__device__ int g_cur[NN];           // seeded with offsets by k_scan
__device__ int g_off[NN + 1];
__device__ int g_psrc[EE];
__device__ float g_eac[(size_t)EE * EDIM];   // edge_attr in CSR order
__device__ u64 g_look[64];

// ---------------- zero all accumulators ----------------
__global__ void k_zero() {
    int i = blockIdx.x * blockDim.x + threadIdx.x;
    if (i < NN) g_deg[i] = 0;
    if (i < 3 * HH) { ((float*)g_sA)[i] = 0.f; ((float*)g_qA)[i] = 0.f; }
    if (i < 2 * H2) { ((float*)g_sB)[i] = 0.f; ((float*)g_qB)[i] = 0.f; }
    if (i < GG * HH) g_pool[i] = 0.f;
    if (i < GG) g_cnt[i] = 0.f;
    if (i < 64) g_look[i] = 0ull;
}

// -------- merged: degree histogram (blocks [0,782)) + input linear ---------
__global__ void k_histlin(const int* __restrict__ ei,
                          const float* __restrict__ x,
                          const float* __restrict__ W,
                          const float* __restrict__ b) {
    __shared__ float Wsh[FIN * HH];       // 8KB
    __shared__ float xs[16][FIN + 1];
    __shared__ float red[4][HH];
    int tid = threadIdx.x;

    if (blockIdx.x < HIST_BLKS) {         // ---- histogram part ----
        int t = blockIdx.x * 256 + tid;
        if (t * 4 < EE) {
            int4 d4 = ((const int4*)(ei + EE))[t];
            atomicAdd(&g_deg[d4.x], 1);
            atomicAdd(&g_deg[d4.y], 1);
            atomicAdd(&g_deg[d4.z], 1);
            atomicAdd(&g_deg[d4.w], 1);
        }
        return;
    }
    // ---- input linear part ----
    int bid = blockIdx.x - HIST_BLKS;
    int j = tid & 63, ig = tid >> 6;      // ig: 0..3

    for (int i = tid; i < FIN * HH; i += 256) Wsh[i] = W[i];
    int n0 = bid * 16;                    // 3125 blocks * 16 = 50000 exactly
    for (int i = tid; i < 16 * FIN; i += 256) {
        int nl = i >> 5, k = i & 31;
        xs[nl][k] = x[(n0 + nl) * FIN + k];
    }
    __syncthreads();

    float bj = b[j];
    float acc[4];
#pragma unroll
    for (int r = 0; r < 4; r++) acc[r] = bj;
#pragma unroll
    for (int k = 0; k < FIN; k++) {
        float wv = Wsh[k * HH + j];
#pragma unroll
        for (int r = 0; r < 4; r++) acc[r] += xs[ig * 4 + r][k] * wv;
    }
    float s = 0.f, q = 0.f;
#pragma unroll
    for (int r = 0; r < 4; r++) {
        g_h[(n0 + ig * 4 + r) * HH + j] = acc[r];
        s += acc[r]; q += acc[r] * acc[r];
    }
    red[ig][j] = s;
    __syncthreads();
    if (ig == 0) {
        float S = red[0][j] + red[1][j] + red[2][j] + red[3][j];
        atomicAdd(&g_sA[0][j], S);
    }
    __syncthreads();
    red[ig][j] = q;
    __syncthreads();
    if (ig == 0) {
        float Q = red[0][j] + red[1][j] + red[2][j] + red[3][j];
        atomicAdd(&g_qA[0][j], Q);
    }
}

// single-kernel scan with decoupled lookback; also seeds g_cur with offsets
__global__ void k_scan() {
    __shared__ int sh[1024];
    __shared__ int exc_sh;
    int b = blockIdx.x, t = threadIdx.x;
    int i = b * 1024 + t;
    int v = (i < NN) ? g_deg[i] : 0;
    sh[t] = v;
    __syncthreads();
    for (int off = 1; off < 1024; off <<= 1) {
        int u = (t >= off) ? sh[t - off] : 0;
        __syncthreads();
        sh[t] += u;
        __syncthreads();
    }
    int total = sh[1023];
    if (t == 0) {
        const u64 FA = 1ull << 62, FP = 2ull << 62;
        if (b == 0) {
            atomicExch(&g_look[0], FP | (u32)total);
            exc_sh = 0;
        } else {
            atomicExch(&g_look[b], FA | (u32)total);
            int run = 0, j = b - 1;
            while (1) {
                u64 s = atomicAdd(&g_look[j], 0ull);
                u64 f = s >> 62;
                if (f == 0) continue;
                int val = (int)(s & 0xFFFFFFFFull);
                run += val;
                if (f == 2) break;
                j--;
            }
            atomicExch(&g_look[b], FP | (u32)(run + total));
            exc_sh = run;
        }
    }
    __syncthreads();
    int e = exc_sh;
    if (i < NN) {
        int off = e + sh[t] - v;   // exclusive
        g_off[i] = off;
        g_cur[i] = off;            // seed for scatter's bump allocation
    }
    if (b == 0 && t == 0) g_off[NN] = EE;
}

// scatter: 1 edge/thread; g_cur holds absolute positions (no g_off load)
__global__ void k_scatter(const int* __restrict__ ei, const float* __restrict__ ea) {
    int e = blockIdx.x * blockDim.x + threadIdx.x;
    if (e >= EE) return;
    int src = __ldg(&ei[e]);
    int d = __ldg(&ei[EE + e]);
    int idx = atomicAdd(&g_cur[d], 1);
    g_psrc[idx] = src;
    const float4* sp = (const float4*)(ea + (size_t)e * EDIM);
    float4 v0 = sp[0], v1 = sp[1], v2 = sp[2], v3 = sp[3];
    float4* dp = (float4*)(g_eac + (size_t)idx * EDIM);
    dp[0] = v0; dp[1] = v1; dp[2] = v2; dp[3] = v3;
}

// ------- CSR-gather: fused BN+ReLU + edge-MLP(f32x2) + softmax-agg + root ---
// one warp per node; lane owns features (2*lane, 2*lane+1); weights in smem
__global__ void k_gather(const float* __restrict__ W, const float* __restrict__ bb,
                         const float* __restrict__ gamma, const float* __restrict__ beta,
                         const float* __restrict__ tptr, int l) {
    __shared__ u64 W0s[256], W1s[256];   // [t2][lane] packed k-pairs
    int tid = threadIdx.x;
    int lane = tid & 31;
    {
        int t2 = tid >> 5;               // 0..7 (256 threads cover all)
        int j0 = 2 * lane;
        float a0 = W[(2 * t2) * HH + j0],     a1 = W[(2 * t2 + 1) * HH + j0];
        float c0 = W[(2 * t2) * HH + j0 + 1], c1 = W[(2 * t2 + 1) * HH + j0 + 1];
        u64 t;
        PACK2(t, __float_as_uint(a0), __float_as_uint(a1)); W0s[t2 * 32 + lane] = t;
        PACK2(t, __float_as_uint(c0), __float_as_uint(c1)); W1s[t2 * 32 + lane] = t;
    }
    __syncthreads();
    int n = (blockIdx.x * blockDim.x + tid) >> 5;
    if (n >= NN) return;
    float tc = tptr[0];
    int j0 = lane * 2;
    // BN constants for the 2 owned features
    float2 sA = *(const float2*)&g_sA[l][j0];
    float2 qA = *(const float2*)&g_qA[l][j0];
    float2 gm = *(const float2*)&gamma[j0];
    float2 bt = *(const float2*)&beta[j0];
    float mu0 = sA.x * (1.f / NN), mu1 = sA.y * (1.f / NN);
    float sc0 = gm.x * rsqrtf(qA.x * (1.f / NN) - mu0 * mu0 + 1e-5f);
    float sc1 = gm.y * rsqrtf(qA.y * (1.f / NN) - mu1 * mu1 + 1e-5f);
    float sf0 = bt.x - mu0 * sc0, sf1 = bt.y - mu1 * sc1;
    u64 scp, sfp;
    PACK2(scp, __float_as_uint(sc0), __float_as_uint(sc1));
    PACK2(sfp, __float_as_uint(sf0), __float_as_uint(sf1));
    float b0 = bb[j0], b1 = bb[j0 + 1];
    int beg = g_off[n], end = g_off[n + 1];
    float den0 = 0.f, num0 = 0.f, den1 = 0.f, num1 = 0.f;
#pragma unroll 4
    for (int i = beg; i < end; i++) {
        int src = __ldg(&g_psrc[i]);
        const ulonglong2* E2 = (const ulonglong2*)(g_eac + (size_t)i * EDIM);
        ulonglong2 p0 = E2[0], p1 = E2[1], p2 = E2[2], p3 = E2[3];
        u64 ev[8] = {p0.x, p0.y, p1.x, p1.y, p2.x, p2.y, p3.x, p3.y};
        u64 acc0 = 0ull, acc1 = 0ull;
#pragma unroll
        for (int t2 = 0; t2 < 8; t2++) {
            FMA2(acc0, ev[t2], W0s[t2 * 32 + lane]);
            FMA2(acc1, ev[t2], W1s[t2 * 32 + lane]);
        }
        u32 lo, hi;
        UNPACK2(lo, hi, acc0);
        float emb0 = b0 + __uint_as_float(lo) + __uint_as_float(hi);
        UNPACK2(lo, hi, acc1);
        float emb1 = b1 + __uint_as_float(lo) + __uint_as_float(hi);
        // z = relu(BN(h[src])) computed on the fly
        u64 h2 = *(const u64*)&g_h[src * HH + j0];
        u64 z2; FMA2D(z2, h2, scp, sfp);
        UNPACK2(lo, hi, z2);
        float z0 = fmaxf(__uint_as_float(lo), 0.f);
        float z1 = fmaxf(__uint_as_float(hi), 0.f);
        float m0 = fmaxf(z0 + emb0, 0.f) + 1e-7f;
        float m1 = fmaxf(z1 + emb1, 0.f) + 1e-7f;
        float ex0 = __expf(m0 * tc);   // no max-shift: m in [1e-7, ~6]
        float ex1 = __expf(m1 * tc);
        den0 += ex0; num0 += ex0 * m0;
        den1 += ex1; num1 += ex1 * m1;
    }
    // root term
    u64 h2 = *(const u64*)&g_h[n * HH + j0];
    u64 z2; FMA2D(z2, h2, scp, sfp);
    u32 lo, hi; UNPACK2(lo, hi, z2);
    float zr0 = fmaxf(__uint_as_float(lo), 0.f);
    float zr1 = fmaxf(__uint_as_float(hi), 0.f);
    float a0 = num0 / (den0 + 1e-16f) + zr0;
    float a1 = num1 / (den1 + 1e-16f) + zr1;
    *(float2*)&g_agg[n * HH + j0] = make_float2(a0, a1);
}

// ------- MLP1 GEMM, f32x2 packed: g_hmid[N,128] = g_agg[N,64] @ w1 + b1 -----
__global__ void k_mlp1(const float* __restrict__ w1, const float* __restrict__ b1, int l) {
    __shared__ float As[64 * 66];       // transposed [k][n]
    __shared__ float sred[8][H2];
    int tid = threadIdx.x;  // 256
    int n0 = blockIdx.x * 64;
    for (int idx = tid; idx < 64 * 16; idx += 256) {
        int r = idx >> 4, c4 = (idx & 15) * 4;
        int gn = n0 + r;
        float4 v = (gn < NN) ? *(const float4*)&g_agg[gn * HH + c4]
                             : make_float4(0.f, 0.f, 0.f, 0.f);
        As[(c4 + 0) * 66 + r] = v.x;
        As[(c4 + 1) * 66 + r] = v.y;
        As[(c4 + 2) * 66 + r] = v.z;
        As[(c4 + 3) * 66 + r] = v.w;
    }
    __syncthreads();
    int tx = tid & 31, ty = tid >> 5;
    int col = tx * 4, row0 = ty * 8;
    u64 acc[4][4];
#pragma unroll
    for (int rp = 0; rp < 4; rp++)
#pragma unroll
        for (int c = 0; c < 4; c++) acc[rp][c] = 0ull;
#pragma unroll 4
    for (int k = 0; k < 64; k++) {
        u64 ap[4];
#pragma unroll
        for (int rp = 0; rp < 4; rp++)
            ap[rp] = *(const u64*)&As[k * 66 + row0 + rp * 2];
        float4 wv = *(const float4*)&w1[k * H2 + col];
#pragma unroll
        for (int c = 0; c < 4; c++) {
            u32 wb = __float_as_uint(((const float*)&wv)[c]);
            u64 wd; PACK2(wd, wb, wb);
#pragma unroll
            for (int rp = 0; rp < 4; rp++) FMA2(acc[rp][c], ap[rp], wd);
        }
    }
    float4 bb = *(const float4*)&b1[col];
    float s[4] = {0.f, 0.f, 0.f, 0.f}, q[4] = {0.f, 0.f, 0.f, 0.f};
#pragma unroll
    for (int rp = 0; rp < 4; rp++) {
        float o0[4], o1[4];
#pragma unroll
        for (int c = 0; c < 4; c++) {
            u32 lo, hi; UNPACK2(lo, hi, acc[rp][c]);
            o0[c] = __uint_as_float(lo) + ((const float*)&bb)[c];
            o1[c] = __uint_as_float(hi) + ((const float*)&bb)[c];
        }
        int na = n0 + row0 + rp * 2;
        if (na < NN) {
            *(float4*)&g_hmid[na * H2 + col] = make_float4(o0[0], o0[1], o0[2], o0[3]);
#pragma unroll
            for (int c = 0; c < 4; c++) { s[c] += o0[c]; q[c] += o0[c] * o0[c]; }
        }
        if (na + 1 < NN) {
            *(float4*)&g_hmid[(na + 1) * H2 + col] = make_float4(o1[0], o1[1], o1[2], o1[3]);
#pragma unroll
            for (int c = 0; c < 4; c++) { s[c] += o1[c]; q[c] += o1[c] * o1[c]; }
        }
    }
#pragma unroll
    for (int c = 0; c < 4; c++) sred[ty][col + c] = s[c];
    __syncthreads();
    if (tid < H2) {
        float S = 0.f;
#pragma unroll
        for (int i = 0; i < 8; i++) S += sred[i][tid];
        atomicAdd(&g_sB[l][tid], S);
    }
    __syncthreads();
#pragma unroll
    for (int c = 0; c < 4; c++) sred[ty][col + c] = q[c];
    __syncthreads();
    if (tid < H2) {
        float Q = 0.f;
#pragma unroll
        for (int i = 0; i < 8; i++) Q += sred[i][tid];
        atomicAdd(&g_qB[l][tid], Q);
    }
}

// ------- MLP2 GEMM, f32x2 packed, fused BN2+ReLU staging + residual --------
__global__ void k_mlp2(const float* __restrict__ w2, const float* __restrict__ b2,
                       const float* __restrict__ gamma, const float* __restrict__ beta,
                       int l) {
    __shared__ float As[H2 * 66];       // transposed [k][n]
    __shared__ float scs[H2], sfs[H2];
    __shared__ float sred[8][HH];
    int tid = threadIdx.x;  // 128
    int n0 = blockIdx.x * 64;
    {   // tid == k
        float mu = g_sB[l][tid] * (1.f / NN);
        float var = g_qB[l][tid] * (1.f / NN) - mu * mu;
        float scr = gamma[tid] * rsqrtf(var + 1e-5f);
        scs[tid] = scr;
        sfs[tid] = beta[tid] - mu * scr;
    }
    __syncthreads();
    for (int idx = tid; idx < 64 * 32; idx += 128) {
        int r = idx >> 5, c4 = (idx & 31) * 4;
        int gn = n0 + r;
        float4 v = (gn < NN) ? *(const float4*)&g_hmid[gn * H2 + c4]
                             : make_float4(0.f, 0.f, 0.f, 0.f);
        As[(c4 + 0) * 66 + r] = fmaxf(v.x * scs[c4]     + sfs[c4],     0.f);
        As[(c4 + 1) * 66 + r] = fmaxf(v.y * scs[c4 + 1] + sfs[c4 + 1], 0.f);
        As[(c4 + 2) * 66 + r] = fmaxf(v.z * scs[c4 + 2] + sfs[c4 + 2], 0.f);
        As[(c4 + 3) * 66 + r] = fmaxf(v.w * scs[c4 + 3] + sfs[c4 + 3], 0.f);
    }
    __syncthreads();
    int tx = tid & 15, ty = tid >> 4;
    int col = tx * 4, row0 = ty * 8;
    u64 acc[4][4];
#pragma unroll
    for (int rp = 0; rp < 4; rp++)
#pragma unroll
        for (int c = 0; c < 4; c++) acc[rp][c] = 0ull;
#pragma unroll 4
    for (int k = 0; k < H2; k++) {
        u64 ap[4];
#pragma unroll
        for (int rp = 0; rp < 4; rp++)
            ap[rp] = *(const u64*)&As[k * 66 + row0 + rp * 2];
        float4 wv = *(const float4*)&w2[k * HH + col];
#pragma unroll
        for (int c = 0; c < 4; c++) {
            u32 wb = __float_as_uint(((const float*)&wv)[c]);
            u64 wd; PACK2(wd, wb, wb);
#pragma unroll
            for (int rp = 0; rp < 4; rp++) FMA2(acc[rp][c], ap[rp], wd);
        }
    }
    float4 bb = *(const float4*)&b2[col];
    float s[4] = {0.f, 0.f, 0.f, 0.f}, q[4] = {0.f, 0.f, 0.f, 0.f};
#pragma unroll
    for (int rp = 0; rp < 4; rp++) {
        float o0[4], o1[4];
#pragma unroll
        for (int c = 0; c < 4; c++) {
            u32 lo, hi; UNPACK2(lo, hi, acc[rp][c]);
            o0[c] = __uint_as_float(lo) + ((const float*)&bb)[c];
            o1[c] = __uint_as_float(hi) + ((const float*)&bb)[c];
        }
        int na = n0 + row0 + rp * 2;
        if (na < NN) {
            float4 h = *(const float4*)&g_h[na * HH + col];
            h.x += o0[0]; h.y += o0[1]; h.z += o0[2]; h.w += o0[3];
            *(float4*)&g_h[na * HH + col] = h;
            s[0] += h.x; s[1] += h.y; s[2] += h.z; s[3] += h.w;
            q[0] += h.x * h.x; q[1] += h.y * h.y; q[2] += h.z * h.z; q[3] += h.w * h.w;
        }
        if (na + 1 < NN) {
            float4 h = *(const float4*)&g_h[(na + 1) * HH + col];
            h.x += o1[0]; h.y += o1[1]; h.z += o1[2]; h.w += o1[3];
            *(float4*)&g_h[(na + 1) * HH + col] = h;
            s[0] += h.x; s[1] += h.y; s[2] += h.z; s[3] += h.w;
            q[0] += h.x * h.x; q[1] += h.y * h.y; q[2] += h.z * h.z; q[3] += h.w * h.w;
        }
    }
#pragma unroll
    for (int c = 0; c < 4; c++) sred[ty][col + c] = s[c];
    __syncthreads();
    if (tid < HH) {
        float S = 0.f;
#pragma unroll
        for (int i = 0; i < 8; i++) S += sred[i][tid];
        atomicAdd(&g_sA[l + 1][tid], S);
    }
    __syncthreads();
#pragma unroll
    for (int c = 0; c < 4; c++) sred[ty][col + c] = q[c];
    __syncthreads();
    if (tid < HH) {
        float Q = 0.f;
#pragma unroll
        for (int i = 0; i < 8; i++) Q += sred[i][tid];
        atomicAdd(&g_qA[l + 1][tid], Q);
    }
}

// ------- global mean pool (batch is sorted): block-chunked segment sum -------
__global__ void k_pool(const int* __restrict__ batch) {
    int j = threadIdx.x;  // 64
    int n0 = blockIdx.x * PCHUNK;
    if (n0 >= NN) return;
    int n1 = min(n0 + PCHUNK, NN);
    int cur = batch[n0];
    float s = 0.f, cnt = 0.f;
    for (int n = n0; n < n1; n++) {
        int b = batch[n];
        if (b != cur) {
            atomicAdd(&g_pool[cur * HH + j], s);
            if (j == 0) atomicAdd(&g_cnt[cur], cnt);
            s = 0.f; cnt = 0.f; cur = b;
        }
        s += g_h[n * HH + j];
        cnt += 1.f;
    }
    atomicAdd(&g_pool[cur * HH + j], s);
    if (j == 0) atomicAdd(&g_cnt[cur], cnt);
}

// ------- output: out = relu(pooled) @ W_out + b_out -------
__global__ void k_final(const float* __restrict__ W, const float* __restrict__ b,
                        float* __restrict__ out) {
    __shared__ float p[HH];
    int g = blockIdx.x, tid = threadIdx.x;  // 64
    float c = fmaxf(g_cnt[g], 1.f);
    p[tid] = fmaxf(g_pool[g * HH + tid] / c, 0.f);
    __syncthreads();
    if (tid < COUT) {
        float acc = b[tid];
#pragma unroll
        for (int k = 0; k < HH; k++) acc += p[k] * W[k * COUT + tid];
        out[g * COUT + tid] = acc;
    }
}

extern "C" void kernel_launch(void* const* d_in, const int* in_sizes, int n_in,
                              void* d_out, int out_size) {
    const float* x        = (const float*)d_in[0];
    const int*   ei       = (const int*)d_in[1];
    const float* ea       = (const float*)d_in[2];
    const int*   batch    = (const int*)d_in[3];
    const float* lin_in_w = (const float*)d_in[4];
    const float* lin_in_b = (const float*)d_in[5];
    const float* ng       = (const float*)d_in[6];
    const float* nb       = (const float*)d_in[7];
    const float* ew       = (const float*)d_in[8];
    const float* eb       = (const float*)d_in[9];
    const float* tt       = (const float*)d_in[10];
    const float* w1       = (const float*)d_in[11];
    const float* b1       = (const float*)d_in[12];
    const float* mg       = (const float*)d_in[13];
    const float* mb       = (const float*)d_in[14];
    const float* w2       = (const float*)d_in[15];
    const float* b2       = (const float*)d_in[16];
    const float* ow       = (const float*)d_in[17];
    const float* ob       = (const float*)d_in[18];
    float* out = (float*)d_out;

    const int SCAN_BLKS = (NN + 1023) / 1024;   // 49

    k_zero<<<(NN + 511) / 512, 512>>>();
    k_histlin<<<HIST_BLKS + LIN_BLKS, 256>>>(ei, x, lin_in_w, lin_in_b);
    k_scan<<<SCAN_BLKS, 1024>>>();
    k_scatter<<<(EE + 255) / 256, 256>>>(ei, ea);   // profiled (4th launch)
    for (int l = 0; l < 2; l++) {
        k_gather<<<(NN * 32 + 255) / 256, 256>>>(ew + l * EDIM * HH, eb + l * HH,
                                                 ng + l * HH, nb + l * HH, tt + l, l);
        k_mlp1<<<(NN + 63) / 64, 256>>>(w1 + l * HH * H2, b1 + l * H2, l);
        k_mlp2<<<(NN + 63) / 64, 128>>>(w2 + l * H2 * HH, b2 + l * HH,
                                        mg + l * H2, mb + l * H2, l);
    }
    k_pool<<<(NN + PCHUNK - 1) / PCHUNK, 64>>>(batch);
    k_final<<<GG, 64>>>(ow, ob, out);
}